// round 9
// baseline (speedup 1.0000x reference)
#include <cuda_runtime.h>
#include <cuda_bf16.h>
#include <math.h>
#include <stdint.h>

// Problem constants
#define NN   4096
#define BB   4
#define DD   4
#define TT   5
#define F1C  32
#define F2C  64
#define CF   256            // BB * F2C columns of cond matrix
#define NSEG (NN / 32)      // 128 u32 words per packed row

// GEMM tiling (full-CF tiles: A read exactly once)
#define MT     64
#define NTF    256                    // all cond columns per CTA
#define KT     32
#define KSPLIT 4
#define NKT4   (NN / KSPLIT / KT)     // 32 k-tiles per CTA
#define LDSB   80                     // 64B row + 16B pad (conflict-free ldsm)
#define ATILE  (MT * LDSB)            // 5120
#define BTILE  (NTF * LDSB)           // 20480
#define GTILE  (ATILE + BTILE)        // 25600
#define GEMM_SMEM (3 * GTILE)         // 76800
#define EPI_SMEM  (17024 * 4)         // 68096

// Scratch (device globals — no allocation allowed)
__device__ float          g_cond[NN * CF];        // cond fp32 [n][b*64+f]
__device__ __nv_bfloat16  g_condT[CF * NN];       // cond bf16 transposed [c][n]
__device__ __nv_bfloat16  g_A16[(size_t)NN * NN]; // dense bf16 adjacency (32 MB)
__device__ unsigned       g_Abits[NN * NSEG];     // bit-packed adjacency
__device__ float          g_invdeg[NN];
__device__ unsigned       g_colOr[NSEG];          // column-nonzero bitmask
__device__ float          g_Spart[KSPLIT][NN * CF]; // K-split partials (4x4MB)

// ---------------------------------------------------------------------------
// helpers
// ---------------------------------------------------------------------------
__device__ __forceinline__ void cp_async16(void* smem_dst, const void* gmem_src) {
    unsigned saddr = (unsigned)__cvta_generic_to_shared(smem_dst);
    asm volatile("cp.async.cg.shared.global [%0], [%1], 16;\n"
                 :: "r"(saddr), "l"(gmem_src) : "memory");
}
__device__ __forceinline__ void cp_async_commit() {
    asm volatile("cp.async.commit_group;\n" ::: "memory");
}
template <int N>
__device__ __forceinline__ void cp_async_wait() {
    asm volatile("cp.async.wait_group %0;\n" :: "n"(N) : "memory");
}
__device__ __forceinline__ void ldsm_x4(uint32_t &r0, uint32_t &r1,
                                        uint32_t &r2, uint32_t &r3,
                                        uint32_t saddr) {
    asm volatile("ldmatrix.sync.aligned.m8n8.x4.shared.b16 {%0,%1,%2,%3}, [%4];\n"
                 : "=r"(r0), "=r"(r1), "=r"(r2), "=r"(r3) : "r"(saddr));
}
__device__ __forceinline__ void mma_bf16_v(float c[4],
    uint32_t a0, uint32_t a1, uint32_t a2, uint32_t a3,
    uint32_t b0, uint32_t b1)
{
    asm volatile(
        "mma.sync.aligned.m16n8k16.row.col.f32.bf16.bf16.f32 "
        "{%0,%1,%2,%3}, {%4,%5,%6,%7}, {%8,%9}, {%0,%1,%2,%3};\n"
        : "+f"(c[0]), "+f"(c[1]), "+f"(c[2]), "+f"(c[3])
        : "r"(a0), "r"(a1), "r"(a2), "r"(a3), "r"(b0), "r"(b1));
}
__device__ __forceinline__ void fma2(float2 &a, const float2 &x, const float2 &y) {
    unsigned long long &ar = reinterpret_cast<unsigned long long &>(a);
    const unsigned long long &xr = reinterpret_cast<const unsigned long long &>(x);
    const unsigned long long &yr = reinterpret_cast<const unsigned long long &>(y);
    asm("fma.rn.f32x2 %0, %1, %2, %0;" : "+l"(ar) : "l"(xr), "l"(yr));
}

// ---------------------------------------------------------------------------
// Fused kernel 1: CTAs [0,512) = prep, CTAs [512,1024) = temporal conv.
// (unchanged from round 8)
// ---------------------------------------------------------------------------
struct CondSmem {
    float sW1[3 * DD * F1C];
    float sW2t[3 * 64 * 36];
    float sb1[F1C];
    float sb2[F2C];
    float sx[8][20];
    float sh[8][96];
    __nv_bfloat16 scT[CF][8];
};

__global__ __launch_bounds__(256) void fused_prep_cond(
    const int*   __restrict__ edges,
    const float* __restrict__ ts,
    const float* __restrict__ Wc1, const float* __restrict__ bc1,
    const float* __restrict__ Wc2, const float* __restrict__ bc2)
{
    __shared__ __align__(16) char pool[sizeof(CondSmem)];
    const int tid  = threadIdx.x;
    const int wid  = tid >> 5;
    const int lane = tid & 31;

    if (blockIdx.x < 512) {
        unsigned* sOr = (unsigned*)pool;
        for (int i = tid; i < NSEG; i += 256) sOr[i] = 0u;
        __syncthreads();

        const int j = blockIdx.x * 8 + wid;
        const int* row = edges + (size_t)j * NN;
        int deg = 0;

        #pragma unroll 1
        for (int it = 0; it < 8; it++) {
            const int k0 = it * 512 + lane * 16;
            int4 v0 = *(const int4*)(row + k0);
            int4 v1 = *(const int4*)(row + k0 + 4);
            int4 v2 = *(const int4*)(row + k0 + 8);
            int4 v3 = *(const int4*)(row + k0 + 12);
            int e[16] = {v0.x,v0.y,v0.z,v0.w, v1.x,v1.y,v1.z,v1.w,
                         v2.x,v2.y,v2.z,v2.w, v3.x,v3.y,v3.z,v3.w};
            unsigned bits = 0;
            #pragma unroll
            for (int i = 0; i < 16; i++) bits |= (e[i] != 0 ? 1u : 0u) << i;
            deg += __popc(bits);

            uint32_t p[8];
            #pragma unroll
            for (int i = 0; i < 8; i++)
                p[i] = ((bits >> (2*i)) & 1u ? 0x3F80u : 0u)
                     | ((bits >> (2*i+1)) & 1u ? 0x3F800000u : 0u);
            uint4* dst = (uint4*)(g_A16 + (size_t)j * NN + k0);
            dst[0] = make_uint4(p[0], p[1], p[2], p[3]);
            dst[1] = make_uint4(p[4], p[5], p[6], p[7]);

            unsigned hi = __shfl_down_sync(0xffffffffu, bits, 1);
            if ((lane & 1) == 0) {
                const unsigned w = bits | (hi << 16);
                const int seg = it * 16 + (lane >> 1);
                g_Abits[(size_t)j * NSEG + seg] = w;
                if (w) atomicOr(&sOr[seg], w);
            }
        }
        #pragma unroll
        for (int off = 16; off > 0; off >>= 1)
            deg += __shfl_down_sync(0xffffffffu, deg, off);
        if (lane == 0) g_invdeg[j] = 1.0f / fmaxf((float)deg, 1.0f);
        __syncthreads();
        for (int i = tid; i < NSEG; i += 256)
            if (sOr[i]) atomicOr(&g_colOr[i], sOr[i]);
    } else {
        CondSmem* cs = (CondSmem*)pool;
        const int n0 = (blockIdx.x - 512) * 8;

        for (int i = tid; i < 3 * F1C * F2C; i += 256) {
            int f = i & 63;
            int pc = i >> 6;
            int p = pc >> 5, c = pc & 31;
            cs->sW2t[(p * 64 + f) * 36 + c] = Wc2[i];
        }
        for (int i = tid; i < 3 * DD * F1C; i += 256) cs->sW1[i] = Wc1[i];
        if (tid < F1C) cs->sb1[tid] = bc1[tid];
        if (tid < F2C) cs->sb2[tid] = bc2[tid];
        __syncthreads();

        for (int it = 0; it < 4; it++) {
            const int item = wid * 4 + it;
            const int b    = item >> 3;
            const int nloc = item & 7;
            const int n    = n0 + nloc;

            if (lane < TT * DD) {
                int t = lane >> 2, d = lane & 3;
                cs->sx[wid][lane] = ts[((size_t)(b * TT + t) * NN + n) * DD + d];
            }
            __syncwarp();

            #pragma unroll
            for (int p = 0; p < 3; p++) {
                float s = cs->sb1[lane];
                #pragma unroll
                for (int r = 0; r < 3; r++)
                    #pragma unroll
                    for (int d = 0; d < DD; d++)
                        s += cs->sx[wid][(p + r) * DD + d]
                           * cs->sW1[(r * DD + d) * F1C + lane];
                cs->sh[wid][p * 32 + lane] = fmaxf(s, 0.f);
            }
            __syncwarp();

            float s0 = cs->sb2[lane], s1 = cs->sb2[lane + 32];
            #pragma unroll
            for (int p = 0; p < 3; p++) {
                const float4* h4 = (const float4*)&cs->sh[wid][p * 32];
                const float4* wa = (const float4*)&cs->sW2t[(p * 64 + lane) * 36];
                const float4* wb = (const float4*)&cs->sW2t[(p * 64 + lane + 32) * 36];
                #pragma unroll
                for (int q = 0; q < 8; q++) {
                    float4 h = h4[q], a = wa[q], bq = wb[q];
                    s0 += h.x * a.x + h.y * a.y + h.z * a.z + h.w * a.w;
                    s1 += h.x * bq.x + h.y * bq.y + h.z * bq.z + h.w * bq.w;
                }
            }
            const int cc0 = b * F2C + lane;
            g_cond[(size_t)n * CF + cc0]      = s0;
            g_cond[(size_t)n * CF + cc0 + 32] = s1;
            cs->scT[cc0][nloc]      = __float2bfloat16(s0);
            cs->scT[cc0 + 32][nloc] = __float2bfloat16(s1);
            __syncwarp();
        }
        __syncthreads();

        if (tid < CF)
            *(int4*)&g_condT[(size_t)tid * NN + n0] = *(int4*)&cs->scT[tid][0];
    }
}

// ---------------------------------------------------------------------------
// Kernel 2: K-split partial GEMM S = A @ cond over ALL 256 cond columns.
// grid (64 row-groups, 4 k-splits) x 256 threads.
// CTA: 64 rows x 256 cols x K=1024. Warp tile m32 x n64. KT=32.
// A16 is read exactly once across the whole grid.
// ---------------------------------------------------------------------------
__global__ __launch_bounds__(256, 2) void gemm_kernel(float* __restrict__ dummy)
{
    extern __shared__ char smem[];
    const unsigned smem_u = (unsigned)__cvta_generic_to_shared(smem);

    const int tid  = threadIdx.x;
    const int wid  = tid >> 5;
    const int lane = tid & 31;
    const int g    = lane >> 2;
    const int t    = lane & 3;
    const int mi2  = wid >> 2;            // 0..1 -> m32 block
    const int nj   = wid & 3;             // 0..3 -> n64 block
    const int j0   = blockIdx.x * MT;
    const int z    = blockIdx.y;
    const int ks0  = z * (NN / KSPLIT);

    const int aoff = (mi2 * 32 + ((lane >> 3) & 1) * 8 + (lane & 7)) * LDSB
                   + (lane >> 4) * 16;
    const int boff = (nj * 64 + (lane >> 4) * 8 + (lane & 7)) * LDSB
                   + ((lane >> 3) & 1) * 16;

    float acc[2][8][4] = {};

    // stage loader: A (64 rows x 64B) + B (256 rows x 64B); 1280 16B chunks
    auto load_stage = [&](int slot, int kt_abs) {
        char* base = smem + slot * GTILE;
        const int k = ks0 + kt_abs * KT;
        #pragma unroll
        for (int u = 0; u < 5; u++) {
            const int ch = u * 256 + tid;
            if (ch < 256) {
                const int rw = ch >> 2, off = ch & 3;
                cp_async16(base + rw * LDSB + off * 16,
                           g_A16 + (size_t)(j0 + rw) * NN + k + off * 8);
            } else {
                const int c2 = ch - 256;
                const int rw = c2 >> 2, off = c2 & 3;
                cp_async16(base + ATILE + rw * LDSB + off * 16,
                           g_condT + (size_t)rw * NN + k + off * 8);
            }
        }
        cp_async_commit();
    };

    load_stage(0, 0);
    load_stage(1, 1);
    cp_async_wait<1>();
    __syncthreads();

    #pragma unroll 1
    for (int kt = 0; kt < NKT4; kt++) {
        if (kt + 2 < NKT4) load_stage((kt + 2) % 3, kt + 2);

        const unsigned Au = smem_u + (kt % 3) * GTILE;
        const unsigned Bu = Au + ATILE;

        #pragma unroll
        for (int kk = 0; kk < 2; kk++) {
            const int kb = kk * 32;
            uint32_t a0[4], a1[4];
            ldsm_x4(a0[0], a0[1], a0[2], a0[3], Au + aoff + kb);
            ldsm_x4(a1[0], a1[1], a1[2], a1[3], Au + aoff + 16 * LDSB + kb);
            #pragma unroll
            for (int nb = 0; nb < 4; nb++) {
                uint32_t b[4];
                ldsm_x4(b[0], b[1], b[2], b[3],
                        Bu + boff + nb * 16 * LDSB + kb);
                mma_bf16_v(acc[0][nb * 2],     a0[0], a0[1], a0[2], a0[3], b[0], b[1]);
                mma_bf16_v(acc[0][nb * 2 + 1], a0[0], a0[1], a0[2], a0[3], b[2], b[3]);
                mma_bf16_v(acc[1][nb * 2],     a1[0], a1[1], a1[2], a1[3], b[0], b[1]);
                mma_bf16_v(acc[1][nb * 2 + 1], a1[0], a1[1], a1[2], a1[3], b[2], b[3]);
            }
        }
        if (kt + 2 < NKT4) cp_async_wait<1>(); else cp_async_wait<0>();
        __syncthreads();
    }

    // store partials
    float* Sp = g_Spart[z];
    #pragma unroll
    for (int h = 0; h < 2; h++) {
        const int r = mi2 * 32 + h * 16 + g;
        #pragma unroll
        for (int ni = 0; ni < 8; ni++) {
            const int col = nj * 64 + ni * 8 + 2 * t;
            *(float2*)&Sp[(size_t)(j0 + r) * CF + col] =
                make_float2(acc[h][ni][0], acc[h][ni][1]);
            *(float2*)&Sp[(size_t)(j0 + r + 8) * CF + col] =
                make_float2(acc[h][ni][2], acc[h][ni][3]);
        }
    }
}

// ---------------------------------------------------------------------------
// Kernel 3: epilogue — combine K-split partials + GEMV chain.
// grid (4, 64) x 256 threads.
// ---------------------------------------------------------------------------
__global__ __launch_bounds__(256) void epi_kernel(
    const float* __restrict__ ts,
    const float* __restrict__ Wg1, const float* __restrict__ bg,
    const float* __restrict__ Wd,  const float* __restrict__ bd,
    const float* __restrict__ Wo,  const float* __restrict__ bo,
    float* __restrict__ out)
{
    extern __shared__ float sm[];
    float* agg  = sm;            // [r][c] 4096 -> later G
    float* cnd  = sm + 4096;     // [r][c] 4096 -> later H
    float* sW   = sm + 8192;     // 8192: Wg1 then Wd
    float* sWo  = sm + 16384;    // 256
    float* sbg  = sm + 16640;
    float* sbd  = sm + 16704;
    float* sbo  = sm + 16768;
    float* sinv = sm + 16832;
    float* sal  = sm + 16896;
    float* sdg  = sm + 16960;

    const int tid = threadIdx.x;
    const int b   = blockIdx.x;
    const int j0  = blockIdx.y * 64;
    const int cb  = b * 64;

    if (tid < 64) {
        const int j = j0 + tid;
        sinv[tid] = g_invdeg[j];
        unsigned dw = g_Abits[(size_t)j * NSEG + (j >> 5)];
        sdg[tid] = ((dw >> (j & 31)) & 1u) ? 1.f : 0.f;
        unsigned aw = g_colOr[j >> 5];
        sal[tid] = ((aw >> (j & 31)) & 1u) ? 1.f : 0.f;
    }
    for (int i = tid; i < 4096; i += 256) sW[i] = Wg1[i];
    if (tid < 256) sWo[tid] = Wo[tid];
    if (tid < 64) { sbg[tid] = bg[tid]; sbd[tid] = bd[tid]; }
    if (tid < 4)  sbo[tid] = bo[tid];
    __syncthreads();

    for (int idx = tid; idx < 4096; idx += 256) {
        const int r = idx >> 6, c = idx & 63;
        const size_t gix = (size_t)(j0 + r) * CF + cb + c;
        const float cv = g_cond[gix];
        const float s  = g_Spart[0][gix] + g_Spart[1][gix]
                       + g_Spart[2][gix] + g_Spart[3][gix];
        cnd[r * 64 + c] = cv;
        agg[r * 64 + c] = (s - sdg[r] * cv) * sinv[r];
    }
    __syncthreads();

    const int fq = tid & 15, rq = tid >> 4;
    const int f0 = fq * 4, r0 = rq * 4;

    // ---- stage 1: G = tanh(agg @ Wg1 + bg) * alive ----
    float2 ac[4][2] = {};
    #pragma unroll 4
    for (int i = 0; i < 64; i++) {
        float4 wv = *(const float4*)&sW[i * 64 + f0];
        float2 w0 = make_float2(wv.x, wv.y), w1 = make_float2(wv.z, wv.w);
        float a0 = agg[(r0 + 0) * 64 + i];
        float a1 = agg[(r0 + 1) * 64 + i];
        float a2 = agg[(r0 + 2) * 64 + i];
        float a3 = agg[(r0 + 3) * 64 + i];
        float2 d0 = make_float2(a0, a0), d1 = make_float2(a1, a1);
        float2 d2 = make_float2(a2, a2), d3 = make_float2(a3, a3);
        fma2(ac[0][0], d0, w0); fma2(ac[0][1], d0, w1);
        fma2(ac[1][0], d1, w0); fma2(ac[1][1], d1, w1);
        fma2(ac[2][0], d2, w0); fma2(ac[2][1], d2, w1);
        fma2(ac[3][0], d3, w0); fma2(ac[3][1], d3, w1);
    }
    float Gv[4][4];
    #pragma unroll
    for (int ri = 0; ri < 4; ri++) {
        const float al = sal[r0 + ri];
        Gv[ri][0] = tanhf(ac[ri][0].x + sbg[f0 + 0]) * al;
        Gv[ri][1] = tanhf(ac[ri][0].y + sbg[f0 + 1]) * al;
        Gv[ri][2] = tanhf(ac[ri][1].x + sbg[f0 + 2]) * al;
        Gv[ri][3] = tanhf(ac[ri][1].y + sbg[f0 + 3]) * al;
    }
    __syncthreads();
    #pragma unroll
    for (int ri = 0; ri < 4; ri++)
        *(float4*)&agg[(r0 + ri) * 64 + f0] =
            make_float4(Gv[ri][0], Gv[ri][1], Gv[ri][2], Gv[ri][3]);
    for (int i = tid; i < 8192; i += 256) sW[i] = Wd[i];
    __syncthreads();

    // ---- stage 2: H = relu([cond, G] @ Wd + bd) ----
    float2 hc[4][2] = {};
    #pragma unroll 4
    for (int i = 0; i < 64; i++) {
        float4 wv = *(const float4*)&sW[i * 64 + f0];
        float2 w0 = make_float2(wv.x, wv.y), w1 = make_float2(wv.z, wv.w);
        float c0v = cnd[(r0 + 0) * 64 + i];
        float c1v = cnd[(r0 + 1) * 64 + i];
        float c2v = cnd[(r0 + 2) * 64 + i];
        float c3v = cnd[(r0 + 3) * 64 + i];
        float2 d0 = make_float2(c0v, c0v), d1 = make_float2(c1v, c1v);
        float2 d2 = make_float2(c2v, c2v), d3 = make_float2(c3v, c3v);
        fma2(hc[0][0], d0, w0); fma2(hc[0][1], d0, w1);
        fma2(hc[1][0], d1, w0); fma2(hc[1][1], d1, w1);
        fma2(hc[2][0], d2, w0); fma2(hc[2][1], d2, w1);
        fma2(hc[3][0], d3, w0); fma2(hc[3][1], d3, w1);
    }
    #pragma unroll 4
    for (int i = 0; i < 64; i++) {
        float4 wv = *(const float4*)&sW[(64 + i) * 64 + f0];
        float2 w0 = make_float2(wv.x, wv.y), w1 = make_float2(wv.z, wv.w);
        float g0 = agg[(r0 + 0) * 64 + i];
        float g1 = agg[(r0 + 1) * 64 + i];
        float g2 = agg[(r0 + 2) * 64 + i];
        float g3 = agg[(r0 + 3) * 64 + i];
        float2 d0 = make_float2(g0, g0), d1 = make_float2(g1, g1);
        float2 d2 = make_float2(g2, g2), d3 = make_float2(g3, g3);
        fma2(hc[0][0], d0, w0); fma2(hc[0][1], d0, w1);
        fma2(hc[1][0], d1, w0); fma2(hc[1][1], d1, w1);
        fma2(hc[2][0], d2, w0); fma2(hc[2][1], d2, w1);
        fma2(hc[3][0], d3, w0); fma2(hc[3][1], d3, w1);
    }
    float Hv[4][4];
    #pragma unroll
    for (int ri = 0; ri < 4; ri++) {
        Hv[ri][0] = fmaxf(hc[ri][0].x + sbd[f0 + 0], 0.f);
        Hv[ri][1] = fmaxf(hc[ri][0].y + sbd[f0 + 1], 0.f);
        Hv[ri][2] = fmaxf(hc[ri][1].x + sbd[f0 + 2], 0.f);
        Hv[ri][3] = fmaxf(hc[ri][1].y + sbd[f0 + 3], 0.f);
    }
    __syncthreads();
    #pragma unroll
    for (int ri = 0; ri < 4; ri++)
        *(float4*)&cnd[(r0 + ri) * 64 + f0] =
            make_float4(Hv[ri][0], Hv[ri][1], Hv[ri][2], Hv[ri][3]);
    __syncthreads();

    // ---- stage 3: out = last + tanh(H @ Wo + bo) ----
    {
        const int r = tid >> 2, d = tid & 3;
        const int j = j0 + r;
        float o = sbo[d];
        #pragma unroll
        for (int f = 0; f < 64; f++) o += cnd[r * 64 + f] * sWo[f * DD + d];
        const float last = ts[((size_t)(b * TT + 4) * NN + j) * DD + d];
        out[((size_t)b * NN + j) * DD + d] = last + tanhf(o);
    }
}

// ---------------------------------------------------------------------------
// Inputs (metadata order): time_segs, edges, Wc1, bc1, Wc2, bc2,
//                          Wg1, bg, Wd, bd, Wo, bo
// ---------------------------------------------------------------------------
extern "C" void kernel_launch(void* const* d_in, const int* in_sizes, int n_in,
                              void* d_out, int out_size)
{
    const float* ts   = (const float*)d_in[0];
    const int*   edges= (const int*)  d_in[1];
    const float* Wc1  = (const float*)d_in[2];
    const float* bc1  = (const float*)d_in[3];
    const float* Wc2  = (const float*)d_in[4];
    const float* bc2  = (const float*)d_in[5];
    const float* Wg1  = (const float*)d_in[6];
    const float* bg   = (const float*)d_in[7];
    const float* Wd   = (const float*)d_in[8];
    const float* bd   = (const float*)d_in[9];
    const float* Wo   = (const float*)d_in[10];
    const float* bo   = (const float*)d_in[11];
    float* out = (float*)d_out;

    static bool attr_done = false;
    if (!attr_done) {
        cudaFuncSetAttribute(gemm_kernel,
                             cudaFuncAttributeMaxDynamicSharedMemorySize, GEMM_SMEM);
        cudaFuncSetAttribute(epi_kernel,
                             cudaFuncAttributeMaxDynamicSharedMemorySize, EPI_SMEM);
        attr_done = true;
    }

    fused_prep_cond<<<1024, 256>>>(edges, ts, Wc1, bc1, Wc2, bc2);
    gemm_kernel<<<dim3(NN / MT, KSPLIT), 256, GEMM_SMEM>>>(out);
    epi_kernel<<<dim3(BB, NN / 64), 256, EPI_SMEM>>>(ts, Wg1, bg, Wd, bd,
                                                     Wo, bo, out);
}

// round 10
// speedup vs baseline: 1.0403x; 1.0403x over previous
#include <cuda_runtime.h>
#include <cuda_bf16.h>
#include <math.h>
#include <stdint.h>

// Problem constants
#define NN   4096
#define BB   4
#define DD   4
#define TT   5
#define F1C  32
#define F2C  64
#define CF   256            // BB * F2C columns of cond matrix
#define NSEG (NN / 32)      // 128 u32 words per packed row

// GEMM tiling (full-CF tiles: A read exactly once)
#define MT     64
#define NTF    256
#define KT     32
#define KSPLIT 4
#define NKT4   (NN / KSPLIT / KT)     // 32 k-tiles per CTA
#define LDSB   80
#define ATILE  (MT * LDSB)            // 5120
#define BTILE  (NTF * LDSB)           // 20480
#define GTILE  (ATILE + BTILE)        // 25600
#define GEMM_SMEM (3 * GTILE)         // 76800
#define EPI_SMEM  (17024 * 4)         // 68096
#define PREPCOND_SMEM 64512

// Scratch (device globals — no allocation allowed)
__device__ float          g_cond[NN * CF];        // cond fp32 [n][b*64+f]
__device__ __nv_bfloat16  g_condT[CF * NN];       // cond bf16 transposed [c][n]
__device__ __nv_bfloat16  g_A16[(size_t)NN * NN]; // dense bf16 adjacency (32 MB)
__device__ unsigned       g_Abits[NN * NSEG];     // bit-packed adjacency
__device__ float          g_invdeg[NN];
__device__ unsigned       g_colOr[NSEG];          // column-nonzero bitmask
__device__ float          g_Spart[KSPLIT][NN * CF]; // K-split partials (4x4MB)

// ---------------------------------------------------------------------------
// helpers
// ---------------------------------------------------------------------------
__device__ __forceinline__ void cp_async16(void* smem_dst, const void* gmem_src) {
    unsigned saddr = (unsigned)__cvta_generic_to_shared(smem_dst);
    asm volatile("cp.async.cg.shared.global [%0], [%1], 16;\n"
                 :: "r"(saddr), "l"(gmem_src) : "memory");
}
__device__ __forceinline__ void cp_async_commit() {
    asm volatile("cp.async.commit_group;\n" ::: "memory");
}
template <int N>
__device__ __forceinline__ void cp_async_wait() {
    asm volatile("cp.async.wait_group %0;\n" :: "n"(N) : "memory");
}
__device__ __forceinline__ void ldsm_x4(uint32_t &r0, uint32_t &r1,
                                        uint32_t &r2, uint32_t &r3,
                                        uint32_t saddr) {
    asm volatile("ldmatrix.sync.aligned.m8n8.x4.shared.b16 {%0,%1,%2,%3}, [%4];\n"
                 : "=r"(r0), "=r"(r1), "=r"(r2), "=r"(r3) : "r"(saddr));
}
__device__ __forceinline__ void mma_bf16_v(float c[4],
    uint32_t a0, uint32_t a1, uint32_t a2, uint32_t a3,
    uint32_t b0, uint32_t b1)
{
    asm volatile(
        "mma.sync.aligned.m16n8k16.row.col.f32.bf16.bf16.f32 "
        "{%0,%1,%2,%3}, {%4,%5,%6,%7}, {%8,%9}, {%0,%1,%2,%3};\n"
        : "+f"(c[0]), "+f"(c[1]), "+f"(c[2]), "+f"(c[3])
        : "r"(a0), "r"(a1), "r"(a2), "r"(a3), "r"(b0), "r"(b1));
}
__device__ __forceinline__ void fma2(float2 &a, const float2 &x, const float2 &y) {
    unsigned long long &ar = reinterpret_cast<unsigned long long &>(a);
    const unsigned long long &xr = reinterpret_cast<const unsigned long long &>(x);
    const unsigned long long &yr = reinterpret_cast<const unsigned long long &>(y);
    asm("fma.rn.f32x2 %0, %1, %2, %0;" : "+l"(ar) : "l"(xr), "l"(yr));
}

// ---------------------------------------------------------------------------
// Fused kernel 1: CTAs [0,512) = prep (unchanged), CTAs [512,768) = cond v2.
// cond v2: 64 items/CTA (16 n x 4 b); conv1 with register-cached W1 column;
// conv2 as epi-style 4x4 register-blocked GEMV with fma2.
// ---------------------------------------------------------------------------
__global__ __launch_bounds__(256) void fused_prep_cond(
    const int*   __restrict__ edges,
    const float* __restrict__ ts,
    const float* __restrict__ Wc1, const float* __restrict__ bc1,
    const float* __restrict__ Wc2, const float* __restrict__ bc2)
{
    extern __shared__ __align__(16) float pool[];
    const int tid  = threadIdx.x;
    const int wid  = tid >> 5;
    const int lane = tid & 31;

    if (blockIdx.x < 512) {
        // ---------------- prep (unchanged) ----------------
        unsigned* sOr = (unsigned*)pool;
        for (int i = tid; i < NSEG; i += 256) sOr[i] = 0u;
        __syncthreads();

        const int j = blockIdx.x * 8 + wid;
        const int* row = edges + (size_t)j * NN;
        int deg = 0;

        #pragma unroll 1
        for (int it = 0; it < 8; it++) {
            const int k0 = it * 512 + lane * 16;
            int4 v0 = *(const int4*)(row + k0);
            int4 v1 = *(const int4*)(row + k0 + 4);
            int4 v2 = *(const int4*)(row + k0 + 8);
            int4 v3 = *(const int4*)(row + k0 + 12);
            int e[16] = {v0.x,v0.y,v0.z,v0.w, v1.x,v1.y,v1.z,v1.w,
                         v2.x,v2.y,v2.z,v2.w, v3.x,v3.y,v3.z,v3.w};
            unsigned bits = 0;
            #pragma unroll
            for (int i = 0; i < 16; i++) bits |= (e[i] != 0 ? 1u : 0u) << i;
            deg += __popc(bits);

            uint32_t p[8];
            #pragma unroll
            for (int i = 0; i < 8; i++)
                p[i] = ((bits >> (2*i)) & 1u ? 0x3F80u : 0u)
                     | ((bits >> (2*i+1)) & 1u ? 0x3F800000u : 0u);
            uint4* dst = (uint4*)(g_A16 + (size_t)j * NN + k0);
            dst[0] = make_uint4(p[0], p[1], p[2], p[3]);
            dst[1] = make_uint4(p[4], p[5], p[6], p[7]);

            unsigned hi = __shfl_down_sync(0xffffffffu, bits, 1);
            if ((lane & 1) == 0) {
                const unsigned w = bits | (hi << 16);
                const int seg = it * 16 + (lane >> 1);
                g_Abits[(size_t)j * NSEG + seg] = w;
                if (w) atomicOr(&sOr[seg], w);
            }
        }
        #pragma unroll
        for (int off = 16; off > 0; off >>= 1)
            deg += __shfl_down_sync(0xffffffffu, deg, off);
        if (lane == 0) g_invdeg[j] = 1.0f / fmaxf((float)deg, 1.0f);
        __syncthreads();
        for (int i = tid; i < NSEG; i += 256)
            if (sOr[i]) atomicOr(&g_colOr[i], sOr[i]);
    } else {
        // ---------------- cond v2 ----------------
        // smem layout (floats):
        float* sW1 = pool;                 // 384
        float* sW2 = pool + 384;           // 6144
        float* sb1 = pool + 6528;          // 32
        float* sb2 = pool + 6560;          // 64
        float* sx  = pool + 6624;          // 64 x 20 = 1280
        float* sh  = pool + 7904;          // 64 x 96 = 6144
        __nv_bfloat16* scT = (__nv_bfloat16*)(pool + 14048); // 256 x 16 bf16

        const int n0 = (blockIdx.x - 512) * 16;

        for (int i = tid; i < 3 * DD * F1C; i += 256) sW1[i] = Wc1[i];
        for (int i = tid; i < 3 * F1C * F2C; i += 256) sW2[i] = Wc2[i];
        if (tid < F1C) sb1[tid] = bc1[tid];
        else if (tid < F1C + F2C) sb2[tid - F1C] = bc2[tid - F1C];

        // stage x: 20 (b,t) rows x 64 floats, coalesced
        for (int i = tid; i < 1280; i += 256) {
            const int bt  = i >> 6;         // b*5 + t
            const int rem = i & 63;         // nloc*4 + d
            const int b = bt / 5, t = bt - b * 5;
            const int nloc = rem >> 2, d = rem & 3;
            sx[(b * 16 + nloc) * 20 + t * 4 + d] =
                ts[(size_t)bt * (NN * 4) + n0 * 4 + rem];
        }
        __syncthreads();

        // ---- phase A: conv1 -> sh[item][96] ----
        {
            const int c4   = (tid & 7) * 4;
            const int slot = tid >> 3;       // 0..31
            float4 w1r[12];
            #pragma unroll
            for (int rd = 0; rd < 12; rd++)
                w1r[rd] = *(const float4*)&sW1[rd * F1C + c4];
            const float4 b1v = *(const float4*)&sb1[c4];

            #pragma unroll
            for (int i = 0; i < 6; i++) {
                const int pair = slot * 6 + i;       // 0..191
                const int item = pair / 3, p = pair - item * 3;
                const float* xp = &sx[item * 20 + p * 4];
                float xv[12];
                *(float4*)&xv[0] = *(const float4*)xp;
                *(float4*)&xv[4] = *(const float4*)(xp + 4);
                *(float4*)&xv[8] = *(const float4*)(xp + 8);
                float4 a = b1v;
                #pragma unroll
                for (int rd = 0; rd < 12; rd++) {
                    a.x += xv[rd] * w1r[rd].x;
                    a.y += xv[rd] * w1r[rd].y;
                    a.z += xv[rd] * w1r[rd].z;
                    a.w += xv[rd] * w1r[rd].w;
                }
                a.x = fmaxf(a.x, 0.f); a.y = fmaxf(a.y, 0.f);
                a.z = fmaxf(a.z, 0.f); a.w = fmaxf(a.w, 0.f);
                *(float4*)&sh[item * 96 + p * 32 + c4] = a;
            }
        }
        __syncthreads();

        // ---- phase B: conv2 (4 items x 4 f per thread, fma2) ----
        {
            const int fq = tid & 15, rq = tid >> 4;
            const int f0 = fq * 4;
            const int it0 = rq * 4;

            float2 ac[4][2] = {};
            #pragma unroll 4
            for (int k = 0; k < 96; k++) {
                float4 wv = *(const float4*)&sW2[k * 64 + f0];
                float2 w0 = make_float2(wv.x, wv.y), w1 = make_float2(wv.z, wv.w);
                float h0 = sh[(it0 + 0) * 96 + k];
                float h1 = sh[(it0 + 1) * 96 + k];
                float h2 = sh[(it0 + 2) * 96 + k];
                float h3 = sh[(it0 + 3) * 96 + k];
                float2 d0 = make_float2(h0, h0), d1 = make_float2(h1, h1);
                float2 d2 = make_float2(h2, h2), d3 = make_float2(h3, h3);
                fma2(ac[0][0], d0, w0); fma2(ac[0][1], d0, w1);
                fma2(ac[1][0], d1, w0); fma2(ac[1][1], d1, w1);
                fma2(ac[2][0], d2, w0); fma2(ac[2][1], d2, w1);
                fma2(ac[3][0], d3, w0); fma2(ac[3][1], d3, w1);
            }
            const float bz0 = sb2[f0], bz1 = sb2[f0 + 1];
            const float bz2 = sb2[f0 + 2], bz3 = sb2[f0 + 3];
            #pragma unroll
            for (int i = 0; i < 4; i++) {
                const int item = it0 + i;
                const int b = item >> 4, nloc = item & 15;
                const int n = n0 + nloc;
                float4 cv;
                cv.x = ac[i][0].x + bz0;
                cv.y = ac[i][0].y + bz1;
                cv.z = ac[i][1].x + bz2;
                cv.w = ac[i][1].y + bz3;
                *(float4*)&g_cond[(size_t)n * CF + b * 64 + f0] = cv;
                scT[(b * 64 + f0 + 0) * 16 + nloc] = __float2bfloat16(cv.x);
                scT[(b * 64 + f0 + 1) * 16 + nloc] = __float2bfloat16(cv.y);
                scT[(b * 64 + f0 + 2) * 16 + nloc] = __float2bfloat16(cv.z);
                scT[(b * 64 + f0 + 3) * 16 + nloc] = __float2bfloat16(cv.w);
            }
        }
        __syncthreads();

        // condT store: 256 rows x 16 bf16 (32B each)
        for (int i = tid; i < 512; i += 256) {
            const int row = i >> 1, half = i & 1;
            *(int4*)((char*)(g_condT + (size_t)row * NN + n0) + half * 16) =
                *(int4*)((char*)(scT + row * 16) + half * 16);
        }
    }
}

// ---------------------------------------------------------------------------
// Kernel 2: K-split partial GEMM S = A @ cond over ALL 256 cond columns.
// grid (64 row-groups, 4 k-splits) x 256 threads. (unchanged from R9)
// ---------------------------------------------------------------------------
__global__ __launch_bounds__(256, 2) void gemm_kernel(float* __restrict__ dummy)
{
    extern __shared__ char smem[];
    const unsigned smem_u = (unsigned)__cvta_generic_to_shared(smem);

    const int tid  = threadIdx.x;
    const int wid  = tid >> 5;
    const int lane = tid & 31;
    const int g    = lane >> 2;
    const int t    = lane & 3;
    const int mi2  = wid >> 2;
    const int nj   = wid & 3;
    const int j0   = blockIdx.x * MT;
    const int z    = blockIdx.y;
    const int ks0  = z * (NN / KSPLIT);

    const int aoff = (mi2 * 32 + ((lane >> 3) & 1) * 8 + (lane & 7)) * LDSB
                   + (lane >> 4) * 16;
    const int boff = (nj * 64 + (lane >> 4) * 8 + (lane & 7)) * LDSB
                   + ((lane >> 3) & 1) * 16;

    float acc[2][8][4] = {};

    auto load_stage = [&](int slot, int kt_abs) {
        char* base = smem + slot * GTILE;
        const int k = ks0 + kt_abs * KT;
        #pragma unroll
        for (int u = 0; u < 5; u++) {
            const int ch = u * 256 + tid;
            if (ch < 256) {
                const int rw = ch >> 2, off = ch & 3;
                cp_async16(base + rw * LDSB + off * 16,
                           g_A16 + (size_t)(j0 + rw) * NN + k + off * 8);
            } else {
                const int c2 = ch - 256;
                const int rw = c2 >> 2, off = c2 & 3;
                cp_async16(base + ATILE + rw * LDSB + off * 16,
                           g_condT + (size_t)rw * NN + k + off * 8);
            }
        }
        cp_async_commit();
    };

    load_stage(0, 0);
    load_stage(1, 1);
    cp_async_wait<1>();
    __syncthreads();

    #pragma unroll 1
    for (int kt = 0; kt < NKT4; kt++) {
        if (kt + 2 < NKT4) load_stage((kt + 2) % 3, kt + 2);

        const unsigned Au = smem_u + (kt % 3) * GTILE;
        const unsigned Bu = Au + ATILE;

        #pragma unroll
        for (int kk = 0; kk < 2; kk++) {
            const int kb = kk * 32;
            uint32_t a0[4], a1[4];
            ldsm_x4(a0[0], a0[1], a0[2], a0[3], Au + aoff + kb);
            ldsm_x4(a1[0], a1[1], a1[2], a1[3], Au + aoff + 16 * LDSB + kb);
            #pragma unroll
            for (int nb = 0; nb < 4; nb++) {
                uint32_t b[4];
                ldsm_x4(b[0], b[1], b[2], b[3],
                        Bu + boff + nb * 16 * LDSB + kb);
                mma_bf16_v(acc[0][nb * 2],     a0[0], a0[1], a0[2], a0[3], b[0], b[1]);
                mma_bf16_v(acc[0][nb * 2 + 1], a0[0], a0[1], a0[2], a0[3], b[2], b[3]);
                mma_bf16_v(acc[1][nb * 2],     a1[0], a1[1], a1[2], a1[3], b[0], b[1]);
                mma_bf16_v(acc[1][nb * 2 + 1], a1[0], a1[1], a1[2], a1[3], b[2], b[3]);
            }
        }
        if (kt + 2 < NKT4) cp_async_wait<1>(); else cp_async_wait<0>();
        __syncthreads();
    }

    float* Sp = g_Spart[z];
    #pragma unroll
    for (int h = 0; h < 2; h++) {
        const int r = mi2 * 32 + h * 16 + g;
        #pragma unroll
        for (int ni = 0; ni < 8; ni++) {
            const int col = nj * 64 + ni * 8 + 2 * t;
            *(float2*)&Sp[(size_t)(j0 + r) * CF + col] =
                make_float2(acc[h][ni][0], acc[h][ni][1]);
            *(float2*)&Sp[(size_t)(j0 + r + 8) * CF + col] =
                make_float2(acc[h][ni][2], acc[h][ni][3]);
        }
    }
}

// ---------------------------------------------------------------------------
// Kernel 3: epilogue — combine K-split partials + GEMV chain. (unchanged)
// ---------------------------------------------------------------------------
__global__ __launch_bounds__(256) void epi_kernel(
    const float* __restrict__ ts,
    const float* __restrict__ Wg1, const float* __restrict__ bg,
    const float* __restrict__ Wd,  const float* __restrict__ bd,
    const float* __restrict__ Wo,  const float* __restrict__ bo,
    float* __restrict__ out)
{
    extern __shared__ float sm[];
    float* agg  = sm;
    float* cnd  = sm + 4096;
    float* sW   = sm + 8192;
    float* sWo  = sm + 16384;
    float* sbg  = sm + 16640;
    float* sbd  = sm + 16704;
    float* sbo  = sm + 16768;
    float* sinv = sm + 16832;
    float* sal  = sm + 16896;
    float* sdg  = sm + 16960;

    const int tid = threadIdx.x;
    const int b   = blockIdx.x;
    const int j0  = blockIdx.y * 64;
    const int cb  = b * 64;

    if (tid < 64) {
        const int j = j0 + tid;
        sinv[tid] = g_invdeg[j];
        unsigned dw = g_Abits[(size_t)j * NSEG + (j >> 5)];
        sdg[tid] = ((dw >> (j & 31)) & 1u) ? 1.f : 0.f;
        unsigned aw = g_colOr[j >> 5];
        sal[tid] = ((aw >> (j & 31)) & 1u) ? 1.f : 0.f;
    }
    for (int i = tid; i < 4096; i += 256) sW[i] = Wg1[i];
    if (tid < 256) sWo[tid] = Wo[tid];
    if (tid < 64) { sbg[tid] = bg[tid]; sbd[tid] = bd[tid]; }
    if (tid < 4)  sbo[tid] = bo[tid];
    __syncthreads();

    for (int idx = tid; idx < 4096; idx += 256) {
        const int r = idx >> 6, c = idx & 63;
        const size_t gix = (size_t)(j0 + r) * CF + cb + c;
        const float cv = g_cond[gix];
        const float s  = g_Spart[0][gix] + g_Spart[1][gix]
                       + g_Spart[2][gix] + g_Spart[3][gix];
        cnd[r * 64 + c] = cv;
        agg[r * 64 + c] = (s - sdg[r] * cv) * sinv[r];
    }
    __syncthreads();

    const int fq = tid & 15, rq = tid >> 4;
    const int f0 = fq * 4, r0 = rq * 4;

    float2 ac[4][2] = {};
    #pragma unroll 4
    for (int i = 0; i < 64; i++) {
        float4 wv = *(const float4*)&sW[i * 64 + f0];
        float2 w0 = make_float2(wv.x, wv.y), w1 = make_float2(wv.z, wv.w);
        float a0 = agg[(r0 + 0) * 64 + i];
        float a1 = agg[(r0 + 1) * 64 + i];
        float a2 = agg[(r0 + 2) * 64 + i];
        float a3 = agg[(r0 + 3) * 64 + i];
        float2 d0 = make_float2(a0, a0), d1 = make_float2(a1, a1);
        float2 d2 = make_float2(a2, a2), d3 = make_float2(a3, a3);
        fma2(ac[0][0], d0, w0); fma2(ac[0][1], d0, w1);
        fma2(ac[1][0], d1, w0); fma2(ac[1][1], d1, w1);
        fma2(ac[2][0], d2, w0); fma2(ac[2][1], d2, w1);
        fma2(ac[3][0], d3, w0); fma2(ac[3][1], d3, w1);
    }
    float Gv[4][4];
    #pragma unroll
    for (int ri = 0; ri < 4; ri++) {
        const float al = sal[r0 + ri];
        Gv[ri][0] = tanhf(ac[ri][0].x + sbg[f0 + 0]) * al;
        Gv[ri][1] = tanhf(ac[ri][0].y + sbg[f0 + 1]) * al;
        Gv[ri][2] = tanhf(ac[ri][1].x + sbg[f0 + 2]) * al;
        Gv[ri][3] = tanhf(ac[ri][1].y + sbg[f0 + 3]) * al;
    }
    __syncthreads();
    #pragma unroll
    for (int ri = 0; ri < 4; ri++)
        *(float4*)&agg[(r0 + ri) * 64 + f0] =
            make_float4(Gv[ri][0], Gv[ri][1], Gv[ri][2], Gv[ri][3]);
    for (int i = tid; i < 8192; i += 256) sW[i] = Wd[i];
    __syncthreads();

    float2 hc[4][2] = {};
    #pragma unroll 4
    for (int i = 0; i < 64; i++) {
        float4 wv = *(const float4*)&sW[i * 64 + f0];
        float2 w0 = make_float2(wv.x, wv.y), w1 = make_float2(wv.z, wv.w);
        float c0v = cnd[(r0 + 0) * 64 + i];
        float c1v = cnd[(r0 + 1) * 64 + i];
        float c2v = cnd[(r0 + 2) * 64 + i];
        float c3v = cnd[(r0 + 3) * 64 + i];
        float2 d0 = make_float2(c0v, c0v), d1 = make_float2(c1v, c1v);
        float2 d2 = make_float2(c2v, c2v), d3 = make_float2(c3v, c3v);
        fma2(hc[0][0], d0, w0); fma2(hc[0][1], d0, w1);
        fma2(hc[1][0], d1, w0); fma2(hc[1][1], d1, w1);
        fma2(hc[2][0], d2, w0); fma2(hc[2][1], d2, w1);
        fma2(hc[3][0], d3, w0); fma2(hc[3][1], d3, w1);
    }
    #pragma unroll 4
    for (int i = 0; i < 64; i++) {
        float4 wv = *(const float4*)&sW[(64 + i) * 64 + f0];
        float2 w0 = make_float2(wv.x, wv.y), w1 = make_float2(wv.z, wv.w);
        float g0 = agg[(r0 + 0) * 64 + i];
        float g1 = agg[(r0 + 1) * 64 + i];
        float g2 = agg[(r0 + 2) * 64 + i];
        float g3 = agg[(r0 + 3) * 64 + i];
        float2 d0 = make_float2(g0, g0), d1 = make_float2(g1, g1);
        float2 d2 = make_float2(g2, g2), d3 = make_float2(g3, g3);
        fma2(hc[0][0], d0, w0); fma2(hc[0][1], d0, w1);
        fma2(hc[1][0], d1, w0); fma2(hc[1][1], d1, w1);
        fma2(hc[2][0], d2, w0); fma2(hc[2][1], d2, w1);
        fma2(hc[3][0], d3, w0); fma2(hc[3][1], d3, w1);
    }
    float Hv[4][4];
    #pragma unroll
    for (int ri = 0; ri < 4; ri++) {
        Hv[ri][0] = fmaxf(hc[ri][0].x + sbd[f0 + 0], 0.f);
        Hv[ri][1] = fmaxf(hc[ri][0].y + sbd[f0 + 1], 0.f);
        Hv[ri][2] = fmaxf(hc[ri][1].x + sbd[f0 + 2], 0.f);
        Hv[ri][3] = fmaxf(hc[ri][1].y + sbd[f0 + 3], 0.f);
    }
    __syncthreads();
    #pragma unroll
    for (int ri = 0; ri < 4; ri++)
        *(float4*)&cnd[(r0 + ri) * 64 + f0] =
            make_float4(Hv[ri][0], Hv[ri][1], Hv[ri][2], Hv[ri][3]);
    __syncthreads();

    {
        const int r = tid >> 2, d = tid & 3;
        const int j = j0 + r;
        float o = sbo[d];
        #pragma unroll
        for (int f = 0; f < 64; f++) o += cnd[r * 64 + f] * sWo[f * DD + d];
        const float last = ts[((size_t)(b * TT + 4) * NN + j) * DD + d];
        out[((size_t)b * NN + j) * DD + d] = last + tanhf(o);
    }
}

// ---------------------------------------------------------------------------
// Inputs (metadata order): time_segs, edges, Wc1, bc1, Wc2, bc2,
//                          Wg1, bg, Wd, bd, Wo, bo
// ---------------------------------------------------------------------------
extern "C" void kernel_launch(void* const* d_in, const int* in_sizes, int n_in,
                              void* d_out, int out_size)
{
    const float* ts   = (const float*)d_in[0];
    const int*   edges= (const int*)  d_in[1];
    const float* Wc1  = (const float*)d_in[2];
    const float* bc1  = (const float*)d_in[3];
    const float* Wc2  = (const float*)d_in[4];
    const float* bc2  = (const float*)d_in[5];
    const float* Wg1  = (const float*)d_in[6];
    const float* bg   = (const float*)d_in[7];
    const float* Wd   = (const float*)d_in[8];
    const float* bd   = (const float*)d_in[9];
    const float* Wo   = (const float*)d_in[10];
    const float* bo   = (const float*)d_in[11];
    float* out = (float*)d_out;

    static bool attr_done = false;
    if (!attr_done) {
        cudaFuncSetAttribute(fused_prep_cond,
                             cudaFuncAttributeMaxDynamicSharedMemorySize, PREPCOND_SMEM);
        cudaFuncSetAttribute(gemm_kernel,
                             cudaFuncAttributeMaxDynamicSharedMemorySize, GEMM_SMEM);
        cudaFuncSetAttribute(epi_kernel,
                             cudaFuncAttributeMaxDynamicSharedMemorySize, EPI_SMEM);
        attr_done = true;
    }

    fused_prep_cond<<<768, 256, PREPCOND_SMEM>>>(edges, ts, Wc1, bc1, Wc2, bc2);
    gemm_kernel<<<dim3(NN / MT, KSPLIT), 256, GEMM_SMEM>>>(out);
    epi_kernel<<<dim3(BB, NN / 64), 256, EPI_SMEM>>>(ts, Wg1, bg, Wd, bd,
                                                     Wo, bo, out);
}

// round 11
// speedup vs baseline: 1.2118x; 1.1648x over previous
#include <cuda_runtime.h>
#include <cuda_bf16.h>
#include <math.h>
#include <stdint.h>

// Problem constants
#define NN   4096
#define BB   4
#define DD   4
#define TT   5
#define F1C  32
#define F2C  64
#define CF   256            // BB * F2C columns of cond matrix
#define NSEG (NN / 32)      // 128 u32 words per packed row

// GEMM tiling
#define MT     64
#define KT     32
#define KSPLIT 4
#define NKT4   (NN / KSPLIT / KT)     // 32 k-tiles per CTA
#define LDSB   80
#define ATILE  (MT * LDSB)            // 5120
#define BTILE  (CF * LDSB)            // 20480
#define GTILE  (ATILE + BTILE)        // 25600
#define GEMM_SMEM (3 * GTILE)         // 76800
#define EPI_SMEM  (17024 * 4)         // 68096
#define PREPCOND_SMEM 64512

// Scratch (device globals — no allocation allowed)
__device__ float          g_cond[NN * CF];        // cond fp32 [n][b*64+f]
__device__ __nv_bfloat16  g_condT[CF * NN];       // cond bf16 transposed [c][n]
__device__ unsigned       g_Abits[NN * NSEG];     // bit-packed adjacency (2MB)
__device__ float          g_invdeg[NN];
__device__ unsigned       g_colOr[NSEG];          // column-nonzero bitmask
__device__ float          g_Spart[KSPLIT][NN * CF]; // K-split partials

// ---------------------------------------------------------------------------
// helpers
// ---------------------------------------------------------------------------
__device__ __forceinline__ void cp_async16(void* smem_dst, const void* gmem_src) {
    unsigned saddr = (unsigned)__cvta_generic_to_shared(smem_dst);
    asm volatile("cp.async.cg.shared.global [%0], [%1], 16;\n"
                 :: "r"(saddr), "l"(gmem_src) : "memory");
}
__device__ __forceinline__ void cp_async_commit() {
    asm volatile("cp.async.commit_group;\n" ::: "memory");
}
template <int N>
__device__ __forceinline__ void cp_async_wait() {
    asm volatile("cp.async.wait_group %0;\n" :: "n"(N) : "memory");
}
__device__ __forceinline__ void ldsm_x4(uint32_t &r0, uint32_t &r1,
                                        uint32_t &r2, uint32_t &r3,
                                        uint32_t saddr) {
    asm volatile("ldmatrix.sync.aligned.m8n8.x4.shared.b16 {%0,%1,%2,%3}, [%4];\n"
                 : "=r"(r0), "=r"(r1), "=r"(r2), "=r"(r3) : "r"(saddr));
}
__device__ __forceinline__ void mma_bf16_v(float c[4],
    uint32_t a0, uint32_t a1, uint32_t a2, uint32_t a3,
    uint32_t b0, uint32_t b1)
{
    asm volatile(
        "mma.sync.aligned.m16n8k16.row.col.f32.bf16.bf16.f32 "
        "{%0,%1,%2,%3}, {%4,%5,%6,%7}, {%8,%9}, {%0,%1,%2,%3};\n"
        : "+f"(c[0]), "+f"(c[1]), "+f"(c[2]), "+f"(c[3])
        : "r"(a0), "r"(a1), "r"(a2), "r"(a3), "r"(b0), "r"(b1));
}
__device__ __forceinline__ void fma2(float2 &a, const float2 &x, const float2 &y) {
    unsigned long long &ar = reinterpret_cast<unsigned long long &>(a);
    const unsigned long long &xr = reinterpret_cast<const unsigned long long &>(x);
    const unsigned long long &yr = reinterpret_cast<const unsigned long long &>(y);
    asm("fma.rn.f32x2 %0, %1, %2, %0;" : "+l"(ar) : "l"(xr), "l"(yr));
}

// ---------------------------------------------------------------------------
// Fused kernel 1: CTAs [0,512) = prep v3 (coalesced loads + shfl bit-pack,
// no dense A16), CTAs [512,768) = cond v2 (unchanged from R10).
// ---------------------------------------------------------------------------
__global__ __launch_bounds__(256) void fused_prep_cond(
    const int*   __restrict__ edges,
    const float* __restrict__ ts,
    const float* __restrict__ Wc1, const float* __restrict__ bc1,
    const float* __restrict__ Wc2, const float* __restrict__ bc2)
{
    extern __shared__ __align__(16) float pool[];
    const int tid  = threadIdx.x;
    const int wid  = tid >> 5;
    const int lane = tid & 31;

    if (blockIdx.x < 512) {
        // ---------------- prep v3: warp per row, coalesced ----------------
        unsigned* sOr = (unsigned*)pool;   // 128 words
        for (int i = tid; i < NSEG; i += 256) sOr[i] = 0u;
        __syncthreads();

        const int j = blockIdx.x * 8 + wid;
        const int* row = edges + (size_t)j * NN;
        const int sh4 = (lane & 7) * 4;
        int deg = 0;

        #pragma unroll 8
        for (int i = 0; i < 32; i++) {
            // warp reads one contiguous 512B chunk: lane gets int4 at lane*4
            int4 v = *(const int4*)(row + i * 128 + lane * 4);
            unsigned nib = (v.x != 0 ? 1u : 0u) | (v.y != 0 ? 2u : 0u)
                         | (v.z != 0 ? 4u : 0u) | (v.w != 0 ? 8u : 0u);
            unsigned w = nib << sh4;
            w |= __shfl_xor_sync(0xffffffffu, w, 1);
            w |= __shfl_xor_sync(0xffffffffu, w, 2);
            w |= __shfl_xor_sync(0xffffffffu, w, 4);
            if ((lane & 7) == 0) {
                const int seg = i * 4 + (lane >> 3);
                g_Abits[(size_t)j * NSEG + seg] = w;
                deg += __popc(w);
                if (w) atomicOr(&sOr[seg], w);
            }
        }
        deg += __shfl_down_sync(0xffffffffu, deg, 16);
        deg += __shfl_down_sync(0xffffffffu, deg, 8);
        if (lane == 0) g_invdeg[j] = 1.0f / fmaxf((float)deg, 1.0f);
        __syncthreads();
        for (int i = tid; i < NSEG; i += 256)
            if (sOr[i]) atomicOr(&g_colOr[i], sOr[i]);
    } else {
        // ---------------- cond v2 (unchanged) ----------------
        float* sW1 = pool;                 // 384
        float* sW2 = pool + 384;           // 6144
        float* sb1 = pool + 6528;          // 32
        float* sb2 = pool + 6560;          // 64
        float* sx  = pool + 6624;          // 64 x 20 = 1280
        float* sh  = pool + 7904;          // 64 x 96 = 6144
        __nv_bfloat16* scT = (__nv_bfloat16*)(pool + 14048); // 256 x 16 bf16

        const int n0 = (blockIdx.x - 512) * 16;

        for (int i = tid; i < 3 * DD * F1C; i += 256) sW1[i] = Wc1[i];
        for (int i = tid; i < 3 * F1C * F2C; i += 256) sW2[i] = Wc2[i];
        if (tid < F1C) sb1[tid] = bc1[tid];
        else if (tid < F1C + F2C) sb2[tid - F1C] = bc2[tid - F1C];

        for (int i = tid; i < 1280; i += 256) {
            const int bt  = i >> 6;
            const int rem = i & 63;
            const int b = bt / 5, t = bt - b * 5;
            const int nloc = rem >> 2, d = rem & 3;
            sx[(b * 16 + nloc) * 20 + t * 4 + d] =
                ts[(size_t)bt * (NN * 4) + n0 * 4 + rem];
        }
        __syncthreads();

        {
            const int c4   = (tid & 7) * 4;
            const int slot = tid >> 3;
            float4 w1r[12];
            #pragma unroll
            for (int rd = 0; rd < 12; rd++)
                w1r[rd] = *(const float4*)&sW1[rd * F1C + c4];
            const float4 b1v = *(const float4*)&sb1[c4];

            #pragma unroll
            for (int i = 0; i < 6; i++) {
                const int pair = slot * 6 + i;
                const int item = pair / 3, p = pair - item * 3;
                const float* xp = &sx[item * 20 + p * 4];
                float xv[12];
                *(float4*)&xv[0] = *(const float4*)xp;
                *(float4*)&xv[4] = *(const float4*)(xp + 4);
                *(float4*)&xv[8] = *(const float4*)(xp + 8);
                float4 a = b1v;
                #pragma unroll
                for (int rd = 0; rd < 12; rd++) {
                    a.x += xv[rd] * w1r[rd].x;
                    a.y += xv[rd] * w1r[rd].y;
                    a.z += xv[rd] * w1r[rd].z;
                    a.w += xv[rd] * w1r[rd].w;
                }
                a.x = fmaxf(a.x, 0.f); a.y = fmaxf(a.y, 0.f);
                a.z = fmaxf(a.z, 0.f); a.w = fmaxf(a.w, 0.f);
                *(float4*)&sh[item * 96 + p * 32 + c4] = a;
            }
        }
        __syncthreads();

        {
            const int fq = tid & 15, rq = tid >> 4;
            const int f0 = fq * 4;
            const int it0 = rq * 4;

            float2 ac[4][2] = {};
            #pragma unroll 4
            for (int k = 0; k < 96; k++) {
                float4 wv = *(const float4*)&sW2[k * 64 + f0];
                float2 w0 = make_float2(wv.x, wv.y), w1 = make_float2(wv.z, wv.w);
                float h0 = sh[(it0 + 0) * 96 + k];
                float h1 = sh[(it0 + 1) * 96 + k];
                float h2 = sh[(it0 + 2) * 96 + k];
                float h3 = sh[(it0 + 3) * 96 + k];
                float2 d0 = make_float2(h0, h0), d1 = make_float2(h1, h1);
                float2 d2 = make_float2(h2, h2), d3 = make_float2(h3, h3);
                fma2(ac[0][0], d0, w0); fma2(ac[0][1], d0, w1);
                fma2(ac[1][0], d1, w0); fma2(ac[1][1], d1, w1);
                fma2(ac[2][0], d2, w0); fma2(ac[2][1], d2, w1);
                fma2(ac[3][0], d3, w0); fma2(ac[3][1], d3, w1);
            }
            const float bz0 = sb2[f0], bz1 = sb2[f0 + 1];
            const float bz2 = sb2[f0 + 2], bz3 = sb2[f0 + 3];
            #pragma unroll
            for (int i = 0; i < 4; i++) {
                const int item = it0 + i;
                const int b = item >> 4, nloc = item & 15;
                const int n = n0 + nloc;
                float4 cv;
                cv.x = ac[i][0].x + bz0;
                cv.y = ac[i][0].y + bz1;
                cv.z = ac[i][1].x + bz2;
                cv.w = ac[i][1].y + bz3;
                *(float4*)&g_cond[(size_t)n * CF + b * 64 + f0] = cv;
                scT[(b * 64 + f0 + 0) * 16 + nloc] = __float2bfloat16(cv.x);
                scT[(b * 64 + f0 + 1) * 16 + nloc] = __float2bfloat16(cv.y);
                scT[(b * 64 + f0 + 2) * 16 + nloc] = __float2bfloat16(cv.z);
                scT[(b * 64 + f0 + 3) * 16 + nloc] = __float2bfloat16(cv.w);
            }
        }
        __syncthreads();

        for (int i = tid; i < 512; i += 256) {
            const int row = i >> 1, half = i & 1;
            *(int4*)((char*)(g_condT + (size_t)row * NN + n0) + half * 16) =
                *(int4*)((char*)(scT + row * 16) + half * 16);
        }
    }
}

// ---------------------------------------------------------------------------
// Kernel 2: K-split partial GEMM S = A @ cond, A expanded in-kernel from
// g_Abits (L2-resident). grid (64 row-groups, 4 k-splits) x 256 threads.
// CTA: 64 rows x 256 cols x K=1024. Warp tile m32 x n64. KT=32.
// ---------------------------------------------------------------------------
__global__ __launch_bounds__(256, 2) void gemm_kernel(float* __restrict__ dummy)
{
    extern __shared__ char smem[];
    const unsigned smem_u = (unsigned)__cvta_generic_to_shared(smem);

    const int tid  = threadIdx.x;
    const int wid  = tid >> 5;
    const int lane = tid & 31;
    const int g    = lane >> 2;
    const int t    = lane & 3;
    const int mi2  = wid >> 2;
    const int nj   = wid & 3;
    const int j0   = blockIdx.x * MT;
    const int z    = blockIdx.y;
    const int ks0  = z * (NN / KSPLIT);

    const int aoff = (mi2 * 32 + ((lane >> 3) & 1) * 8 + (lane & 7)) * LDSB
                   + (lane >> 4) * 16;
    const int boff = (nj * 64 + (lane >> 4) * 8 + (lane & 7)) * LDSB
                   + ((lane >> 3) & 1) * 16;

    // A expansion mapping: 4 threads per row, 8 bits (k) each
    const int erow = tid >> 2;
    const int etq  = tid & 3;
    const unsigned* ebits = g_Abits + (size_t)(j0 + erow) * NSEG + (ks0 >> 5);
    char* const astore_base = smem + erow * LDSB + etq * 16;

    float acc[2][8][4] = {};

    auto load_B = [&](int slot, int kt_abs) {
        char* base = smem + slot * GTILE + ATILE;
        const int k = ks0 + kt_abs * KT;
        #pragma unroll
        for (int u = 0; u < 4; u++) {
            const int ch = u * 256 + tid;
            const int rw = ch >> 2, off = ch & 3;
            cp_async16(base + rw * LDSB + off * 16,
                       g_condT + (size_t)rw * NN + k + off * 8);
        }
        cp_async_commit();
    };
    auto expand_A = [&](int slot, unsigned w) {
        const unsigned bits = (w >> (etq * 8)) & 0xFFu;
        uint32_t p[4];
        #pragma unroll
        for (int i = 0; i < 4; i++)
            p[i] = ((bits >> (2 * i)) & 1u ? 0x3F80u : 0u)
                 | ((bits >> (2 * i + 1)) & 1u ? 0x3F800000u : 0u);
        *(uint4*)(astore_base + slot * GTILE) = make_uint4(p[0], p[1], p[2], p[3]);
    };

    // prologue: stages 0,1
    {
        unsigned w0 = __ldg(ebits + 0);
        unsigned w1 = __ldg(ebits + 1);
        load_B(0, 0);
        load_B(1, 1);
        expand_A(0, w0);
        expand_A(1, w1);
    }
    cp_async_wait<1>();
    __syncthreads();

    #pragma unroll 1
    for (int kt = 0; kt < NKT4; kt++) {
        unsigned wnext = 0;
        if (kt + 2 < NKT4) {
            wnext = __ldg(ebits + kt + 2);
            load_B((kt + 2) % 3, kt + 2);
        }

        const unsigned Au = smem_u + (kt % 3) * GTILE;
        const unsigned Bu = Au + ATILE;

        #pragma unroll
        for (int kk = 0; kk < 2; kk++) {
            const int kb = kk * 32;
            uint32_t a0[4], a1[4];
            ldsm_x4(a0[0], a0[1], a0[2], a0[3], Au + aoff + kb);
            ldsm_x4(a1[0], a1[1], a1[2], a1[3], Au + aoff + 16 * LDSB + kb);
            #pragma unroll
            for (int nb = 0; nb < 4; nb++) {
                uint32_t b[4];
                ldsm_x4(b[0], b[1], b[2], b[3],
                        Bu + boff + nb * 16 * LDSB + kb);
                mma_bf16_v(acc[0][nb * 2],     a0[0], a0[1], a0[2], a0[3], b[0], b[1]);
                mma_bf16_v(acc[0][nb * 2 + 1], a0[0], a0[1], a0[2], a0[3], b[2], b[3]);
                mma_bf16_v(acc[1][nb * 2],     a1[0], a1[1], a1[2], a1[3], b[0], b[1]);
                mma_bf16_v(acc[1][nb * 2 + 1], a1[0], a1[1], a1[2], a1[3], b[2], b[3]);
            }
        }

        if (kt + 2 < NKT4) {
            expand_A((kt + 2) % 3, wnext);
            cp_async_wait<1>();
        } else {
            cp_async_wait<0>();
        }
        __syncthreads();
    }

    float* Sp = g_Spart[z];
    #pragma unroll
    for (int h = 0; h < 2; h++) {
        const int r = mi2 * 32 + h * 16 + g;
        #pragma unroll
        for (int ni = 0; ni < 8; ni++) {
            const int col = nj * 64 + ni * 8 + 2 * t;
            *(float2*)&Sp[(size_t)(j0 + r) * CF + col] =
                make_float2(acc[h][ni][0], acc[h][ni][1]);
            *(float2*)&Sp[(size_t)(j0 + r + 8) * CF + col] =
                make_float2(acc[h][ni][2], acc[h][ni][3]);
        }
    }
}

// ---------------------------------------------------------------------------
// Kernel 3: epilogue — combine K-split partials + GEMV chain. (unchanged)
// ---------------------------------------------------------------------------
__global__ __launch_bounds__(256) void epi_kernel(
    const float* __restrict__ ts,
    const float* __restrict__ Wg1, const float* __restrict__ bg,
    const float* __restrict__ Wd,  const float* __restrict__ bd,
    const float* __restrict__ Wo,  const float* __restrict__ bo,
    float* __restrict__ out)
{
    extern __shared__ float sm[];
    float* agg  = sm;
    float* cnd  = sm + 4096;
    float* sW   = sm + 8192;
    float* sWo  = sm + 16384;
    float* sbg  = sm + 16640;
    float* sbd  = sm + 16704;
    float* sbo  = sm + 16768;
    float* sinv = sm + 16832;
    float* sal  = sm + 16896;
    float* sdg  = sm + 16960;

    const int tid = threadIdx.x;
    const int b   = blockIdx.x;
    const int j0  = blockIdx.y * 64;
    const int cb  = b * 64;

    if (tid < 64) {
        const int j = j0 + tid;
        sinv[tid] = g_invdeg[j];
        unsigned dw = g_Abits[(size_t)j * NSEG + (j >> 5)];
        sdg[tid] = ((dw >> (j & 31)) & 1u) ? 1.f : 0.f;
        unsigned aw = g_colOr[j >> 5];
        sal[tid] = ((aw >> (j & 31)) & 1u) ? 1.f : 0.f;
    }
    for (int i = tid; i < 4096; i += 256) sW[i] = Wg1[i];
    if (tid < 256) sWo[tid] = Wo[tid];
    if (tid < 64) { sbg[tid] = bg[tid]; sbd[tid] = bd[tid]; }
    if (tid < 4)  sbo[tid] = bo[tid];
    __syncthreads();

    for (int idx = tid; idx < 4096; idx += 256) {
        const int r = idx >> 6, c = idx & 63;
        const size_t gix = (size_t)(j0 + r) * CF + cb + c;
        const float cv = g_cond[gix];
        const float s  = g_Spart[0][gix] + g_Spart[1][gix]
                       + g_Spart[2][gix] + g_Spart[3][gix];
        cnd[r * 64 + c] = cv;
        agg[r * 64 + c] = (s - sdg[r] * cv) * sinv[r];
    }
    __syncthreads();

    const int fq = tid & 15, rq = tid >> 4;
    const int f0 = fq * 4, r0 = rq * 4;

    float2 ac[4][2] = {};
    #pragma unroll 4
    for (int i = 0; i < 64; i++) {
        float4 wv = *(const float4*)&sW[i * 64 + f0];
        float2 w0 = make_float2(wv.x, wv.y), w1 = make_float2(wv.z, wv.w);
        float a0 = agg[(r0 + 0) * 64 + i];
        float a1 = agg[(r0 + 1) * 64 + i];
        float a2 = agg[(r0 + 2) * 64 + i];
        float a3 = agg[(r0 + 3) * 64 + i];
        float2 d0 = make_float2(a0, a0), d1 = make_float2(a1, a1);
        float2 d2 = make_float2(a2, a2), d3 = make_float2(a3, a3);
        fma2(ac[0][0], d0, w0); fma2(ac[0][1], d0, w1);
        fma2(ac[1][0], d1, w0); fma2(ac[1][1], d1, w1);
        fma2(ac[2][0], d2, w0); fma2(ac[2][1], d2, w1);
        fma2(ac[3][0], d3, w0); fma2(ac[3][1], d3, w1);
    }
    float Gv[4][4];
    #pragma unroll
    for (int ri = 0; ri < 4; ri++) {
        const float al = sal[r0 + ri];
        Gv[ri][0] = tanhf(ac[ri][0].x + sbg[f0 + 0]) * al;
        Gv[ri][1] = tanhf(ac[ri][0].y + sbg[f0 + 1]) * al;
        Gv[ri][2] = tanhf(ac[ri][1].x + sbg[f0 + 2]) * al;
        Gv[ri][3] = tanhf(ac[ri][1].y + sbg[f0 + 3]) * al;
    }
    __syncthreads();
    #pragma unroll
    for (int ri = 0; ri < 4; ri++)
        *(float4*)&agg[(r0 + ri) * 64 + f0] =
            make_float4(Gv[ri][0], Gv[ri][1], Gv[ri][2], Gv[ri][3]);
    for (int i = tid; i < 8192; i += 256) sW[i] = Wd[i];
    __syncthreads();

    float2 hc[4][2] = {};
    #pragma unroll 4
    for (int i = 0; i < 64; i++) {
        float4 wv = *(const float4*)&sW[i * 64 + f0];
        float2 w0 = make_float2(wv.x, wv.y), w1 = make_float2(wv.z, wv.w);
        float c0v = cnd[(r0 + 0) * 64 + i];
        float c1v = cnd[(r0 + 1) * 64 + i];
        float c2v = cnd[(r0 + 2) * 64 + i];
        float c3v = cnd[(r0 + 3) * 64 + i];
        float2 d0 = make_float2(c0v, c0v), d1 = make_float2(c1v, c1v);
        float2 d2 = make_float2(c2v, c2v), d3 = make_float2(c3v, c3v);
        fma2(hc[0][0], d0, w0); fma2(hc[0][1], d0, w1);
        fma2(hc[1][0], d1, w0); fma2(hc[1][1], d1, w1);
        fma2(hc[2][0], d2, w0); fma2(hc[2][1], d2, w1);
        fma2(hc[3][0], d3, w0); fma2(hc[3][1], d3, w1);
    }
    #pragma unroll 4
    for (int i = 0; i < 64; i++) {
        float4 wv = *(const float4*)&sW[(64 + i) * 64 + f0];
        float2 w0 = make_float2(wv.x, wv.y), w1 = make_float2(wv.z, wv.w);
        float g0 = agg[(r0 + 0) * 64 + i];
        float g1 = agg[(r0 + 1) * 64 + i];
        float g2 = agg[(r0 + 2) * 64 + i];
        float g3 = agg[(r0 + 3) * 64 + i];
        float2 d0 = make_float2(g0, g0), d1 = make_float2(g1, g1);
        float2 d2 = make_float2(g2, g2), d3 = make_float2(g3, g3);
        fma2(hc[0][0], d0, w0); fma2(hc[0][1], d0, w1);
        fma2(hc[1][0], d1, w0); fma2(hc[1][1], d1, w1);
        fma2(hc[2][0], d2, w0); fma2(hc[2][1], d2, w1);
        fma2(hc[3][0], d3, w0); fma2(hc[3][1], d3, w1);
    }
    float Hv[4][4];
    #pragma unroll
    for (int ri = 0; ri < 4; ri++) {
        Hv[ri][0] = fmaxf(hc[ri][0].x + sbd[f0 + 0], 0.f);
        Hv[ri][1] = fmaxf(hc[ri][0].y + sbd[f0 + 1], 0.f);
        Hv[ri][2] = fmaxf(hc[ri][1].x + sbd[f0 + 2], 0.f);
        Hv[ri][3] = fmaxf(hc[ri][1].y + sbd[f0 + 3], 0.f);
    }
    __syncthreads();
    #pragma unroll
    for (int ri = 0; ri < 4; ri++)
        *(float4*)&cnd[(r0 + ri) * 64 + f0] =
            make_float4(Hv[ri][0], Hv[ri][1], Hv[ri][2], Hv[ri][3]);
    __syncthreads();

    {
        const int r = tid >> 2, d = tid & 3;
        const int j = j0 + r;
        float o = sbo[d];
        #pragma unroll
        for (int f = 0; f < 64; f++) o += cnd[r * 64 + f] * sWo[f * DD + d];
        const float last = ts[((size_t)(b * TT + 4) * NN + j) * DD + d];
        out[((size_t)b * NN + j) * DD + d] = last + tanhf(o);
    }
}

// ---------------------------------------------------------------------------
// Inputs (metadata order): time_segs, edges, Wc1, bc1, Wc2, bc2,
//                          Wg1, bg, Wd, bd, Wo, bo
// ---------------------------------------------------------------------------
extern "C" void kernel_launch(void* const* d_in, const int* in_sizes, int n_in,
                              void* d_out, int out_size)
{
    const float* ts   = (const float*)d_in[0];
    const int*   edges= (const int*)  d_in[1];
    const float* Wc1  = (const float*)d_in[2];
    const float* bc1  = (const float*)d_in[3];
    const float* Wc2  = (const float*)d_in[4];
    const float* bc2  = (const float*)d_in[5];
    const float* Wg1  = (const float*)d_in[6];
    const float* bg   = (const float*)d_in[7];
    const float* Wd   = (const float*)d_in[8];
    const float* bd   = (const float*)d_in[9];
    const float* Wo   = (const float*)d_in[10];
    const float* bo   = (const float*)d_in[11];
    float* out = (float*)d_out;

    static bool attr_done = false;
    if (!attr_done) {
        cudaFuncSetAttribute(fused_prep_cond,
                             cudaFuncAttributeMaxDynamicSharedMemorySize, PREPCOND_SMEM);
        cudaFuncSetAttribute(gemm_kernel,
                             cudaFuncAttributeMaxDynamicSharedMemorySize, GEMM_SMEM);
        cudaFuncSetAttribute(epi_kernel,
                             cudaFuncAttributeMaxDynamicSharedMemorySize, EPI_SMEM);
        attr_done = true;
    }

    fused_prep_cond<<<768, 256, PREPCOND_SMEM>>>(edges, ts, Wc1, bc1, Wc2, bc2);
    gemm_kernel<<<dim3(NN / MT, KSPLIT), 256, GEMM_SMEM>>>(out);
    epi_kernel<<<dim3(BB, NN / 64), 256, EPI_SMEM>>>(ts, Wg1, bg, Wd, bd,
                                                     Wo, bo, out);
}

// round 13
// speedup vs baseline: 1.5297x; 1.2623x over previous
#include <cuda_runtime.h>
#include <cuda_bf16.h>
#include <math.h>
#include <stdint.h>

// Problem constants
#define NN   4096
#define BB   4
#define DD   4
#define TT   5
#define F1C  32
#define F2C  64
#define CF   256            // BB * F2C columns of cond matrix
#define NSEG (NN / 32)      // 128 u32 words per packed row

// tcgen05 GEMM tiling
#define TC_M     128
#define TC_N     256                      // all cond columns
#define TC_KT    64                       // 64 bf16 = 128 B per smem row
#define TC_KSPLIT 4
#define TC_NKT   (NN / TC_KSPLIT / TC_KT) // 16 k-tiles per CTA
#define TC_AB    (TC_M * 128)             // 16384
#define TC_BB    (TC_N * 128)             // 32768
#define TC_BUF   (TC_AB + TC_BB)          // 49152
#define TC_SMEM  (2048 + 3 * TC_BUF)      // 149504 (mbar + align slack + bufs)

// fallback (HMMA) tiling inside the same kernel/launch config
#define FB_KT    32
#define FB_NKT   (NN / TC_KSPLIT / FB_KT) // 32
#define FB_LDSB  80
#define FB_AT    (64 * FB_LDSB)           // 5120
#define FB_BT    (CF * FB_LDSB)           // 20480
#define FB_GT    (FB_AT + FB_BT)          // 25600

#define EPI_SMEM  (17024 * 4)             // 68096
#define PREPCOND_SMEM 64512

// idesc: dtype F32, atype/btype BF16, N=256, M=128 (kind::f16)
#define TC_IDESC ((1u<<4) | (1u<<7) | (1u<<10) | ((TC_N/8)<<17) | ((TC_M>>4)<<24))

#define SWZ(x) ((x) ^ (((x) >> 3) & 0x70))

// Scratch (device globals — no allocation allowed)
__device__ float          g_cond[NN * CF];        // cond fp32 [n][b*64+f]
__device__ __nv_bfloat16  g_condT[CF * NN];       // cond bf16 transposed [c][n]
__device__ unsigned       g_Abits[NN * NSEG];     // bit-packed adjacency (2MB)
__device__ float          g_invdeg[NN];
__device__ unsigned       g_colOr[NSEG];          // column-nonzero bitmask
__device__ float          g_Spart[TC_KSPLIT][NN * CF]; // K-split partials

// ---------------------------------------------------------------------------
// helpers (tcgen05 helpers are only referenced from the guarded path, so the
// non-103a passes never emit them)
// ---------------------------------------------------------------------------
__device__ __forceinline__ void cp_async16(void* smem_dst, const void* gmem_src) {
    unsigned saddr = (unsigned)__cvta_generic_to_shared(smem_dst);
    asm volatile("cp.async.cg.shared.global [%0], [%1], 16;\n"
                 :: "r"(saddr), "l"(gmem_src) : "memory");
}
__device__ __forceinline__ void cp_async_commit() {
    asm volatile("cp.async.commit_group;\n" ::: "memory");
}
template <int N>
__device__ __forceinline__ void cp_async_wait() {
    asm volatile("cp.async.wait_group %0;\n" :: "n"(N) : "memory");
}
__device__ __forceinline__ void ldsm_x4(uint32_t &r0, uint32_t &r1,
                                        uint32_t &r2, uint32_t &r3,
                                        uint32_t saddr) {
    asm volatile("ldmatrix.sync.aligned.m8n8.x4.shared.b16 {%0,%1,%2,%3}, [%4];\n"
                 : "=r"(r0), "=r"(r1), "=r"(r2), "=r"(r3) : "r"(saddr));
}
__device__ __forceinline__ void mma_bf16_v(float c[4],
    uint32_t a0, uint32_t a1, uint32_t a2, uint32_t a3,
    uint32_t b0, uint32_t b1)
{
    asm volatile(
        "mma.sync.aligned.m16n8k16.row.col.f32.bf16.bf16.f32 "
        "{%0,%1,%2,%3}, {%4,%5,%6,%7}, {%8,%9}, {%0,%1,%2,%3};\n"
        : "+f"(c[0]), "+f"(c[1]), "+f"(c[2]), "+f"(c[3])
        : "r"(a0), "r"(a1), "r"(a2), "r"(a3), "r"(b0), "r"(b1));
}
__device__ __forceinline__ void fma2(float2 &a, const float2 &x, const float2 &y) {
    unsigned long long &ar = reinterpret_cast<unsigned long long &>(a);
    const unsigned long long &xr = reinterpret_cast<const unsigned long long &>(x);
    const unsigned long long &yr = reinterpret_cast<const unsigned long long &>(y);
    asm("fma.rn.f32x2 %0, %1, %2, %0;" : "+l"(ar) : "l"(xr), "l"(yr));
}
__device__ __forceinline__ uint32_t smem_u32(const void* p) {
    return (uint32_t)__cvta_generic_to_shared(p);
}
__device__ __forceinline__ uint32_t elect_one() {
    uint32_t pred;
    asm volatile("{\n\t.reg .pred p;\n\telect.sync _|p, 0xFFFFFFFF;\n\t"
                 "selp.b32 %0, 1, 0, p;\n\t}" : "=r"(pred));
    return pred;
}
__device__ __forceinline__ uint64_t make_desc_sw128(uint32_t addr) {
    const uint64_t base = (uint64_t(2) << 61) | (uint64_t(1) << 46)
                        | (uint64_t(64) << 32) | (uint64_t(1) << 16);
    return base | ((uint64_t)(addr >> 4) & 0x3FFF);
}
__device__ __forceinline__ void tc_mma_f16_ss(uint32_t d, uint64_t ad,
                                              uint64_t bd, uint32_t idesc,
                                              bool en) {
    uint32_t e = en ? 1u : 0u;
    asm volatile(
        "{\n\t.reg .pred p;\n\tsetp.ne.u32 p, %5, 0;\n\t"
        "tcgen05.mma.cta_group::1.kind::f16 [%0], %1, %2, %3, {%4, %4, %4, %4}, p;\n\t}"
        :: "r"(d), "l"(ad), "l"(bd), "r"(idesc), "r"(0u), "r"(e) : "memory");
}
__device__ __forceinline__ void mbar_init(uint32_t a, uint32_t cnt) {
    asm volatile("mbarrier.init.shared.b64 [%0], %1;" :: "r"(a), "r"(cnt) : "memory");
}
__device__ __forceinline__ void tc_commit(uint32_t mbar) {
    asm volatile(
        "tcgen05.commit.cta_group::1.mbarrier::arrive::one.shared::cluster.b64 [%0];"
        :: "r"(mbar) : "memory");
}
__device__ __forceinline__ void mbar_wait(uint32_t mbar, uint32_t parity) {
    uint32_t done;
    asm volatile(
        "{\n\t.reg .pred p;\n\t"
        "mbarrier.try_wait.parity.acquire.cta.shared::cta.b64 p, [%1], %2;\n\t"
        "selp.b32 %0, 1, 0, p;\n\t}"
        : "=r"(done) : "r"(mbar), "r"(parity) : "memory");
    if (!done) {
        asm volatile(
            "{\n\t.reg .pred P1;\n\t"
            "WL_%=:\n\t"
            "mbarrier.try_wait.parity.acquire.cta.shared::cta.b64 P1, [%0], %1, 0x989680;\n\t"
            "@P1 bra.uni WD_%=;\n\t"
            "bra.uni WL_%=;\n\t"
            "WD_%=:\n\t}"
            :: "r"(mbar), "r"(parity) : "memory");
    }
}
__device__ __forceinline__ void fence_proxy_async_cta() {
    asm volatile("fence.proxy.async.shared::cta;" ::: "memory");
}

// ---------------------------------------------------------------------------
// Fused kernel 1: CTAs [0,512) = prep v4 (ballot), CTAs [512,768) = cond v2.
// ---------------------------------------------------------------------------
__global__ __launch_bounds__(256) void fused_prep_cond(
    const int*   __restrict__ edges,
    const float* __restrict__ ts,
    const float* __restrict__ Wc1, const float* __restrict__ bc1,
    const float* __restrict__ Wc2, const float* __restrict__ bc2)
{
    extern __shared__ __align__(16) float pool[];
    const int tid  = threadIdx.x;
    const int wid  = tid >> 5;
    const int lane = tid & 31;

    if (blockIdx.x < 512) {
        // ---------------- prep v4: warp per row, ballot bit-pack ----------
        unsigned* sOr = (unsigned*)pool;   // 128 words
        for (int i = tid; i < NSEG; i += 256) sOr[i] = 0u;
        __syncthreads();

        const int j = blockIdx.x * 8 + wid;
        const int* row = edges + (size_t)j * NN;
        int deg = 0;

        #pragma unroll 1
        for (int q = 0; q < 4; q++) {
            unsigned kw = 0;
            #pragma unroll
            for (int i2 = 0; i2 < 32; i2++) {
                int v = row[(q * 32 + i2) * 32 + lane];   // warp-contiguous 128B
                unsigned w = __ballot_sync(0xffffffffu, v != 0);
                if (lane == i2) kw = w;
            }
            const int seg = q * 32 + lane;
            g_Abits[(size_t)j * NSEG + seg] = kw;      // coalesced STG
            deg += __popc(kw);
            if (kw) atomicOr(&sOr[seg], kw);
        }
        #pragma unroll
        for (int off = 16; off > 0; off >>= 1)
            deg += __shfl_down_sync(0xffffffffu, deg, off);
        if (lane == 0) g_invdeg[j] = 1.0f / fmaxf((float)deg, 1.0f);
        __syncthreads();
        for (int i = tid; i < NSEG; i += 256)
            if (sOr[i]) atomicOr(&g_colOr[i], sOr[i]);
    } else {
        // ---------------- cond v2 (unchanged) ----------------
        float* sW1 = pool;                 // 384
        float* sW2 = pool + 384;           // 6144
        float* sb1 = pool + 6528;          // 32
        float* sb2 = pool + 6560;          // 64
        float* sx  = pool + 6624;          // 64 x 20 = 1280
        float* sh  = pool + 7904;          // 64 x 96 = 6144
        __nv_bfloat16* scT = (__nv_bfloat16*)(pool + 14048); // 256 x 16 bf16

        const int n0 = (blockIdx.x - 512) * 16;

        for (int i = tid; i < 3 * DD * F1C; i += 256) sW1[i] = Wc1[i];
        for (int i = tid; i < 3 * F1C * F2C; i += 256) sW2[i] = Wc2[i];
        if (tid < F1C) sb1[tid] = bc1[tid];
        else if (tid < F1C + F2C) sb2[tid - F1C] = bc2[tid - F1C];

        for (int i = tid; i < 1280; i += 256) {
            const int bt  = i >> 6;
            const int rem = i & 63;
            const int b = bt / 5, t = bt - b * 5;
            const int nloc = rem >> 2, d = rem & 3;
            sx[(b * 16 + nloc) * 20 + t * 4 + d] =
                ts[(size_t)bt * (NN * 4) + n0 * 4 + rem];
        }
        __syncthreads();

        {
            const int c4   = (tid & 7) * 4;
            const int slot = tid >> 3;
            float4 w1r[12];
            #pragma unroll
            for (int rd = 0; rd < 12; rd++)
                w1r[rd] = *(const float4*)&sW1[rd * F1C + c4];
            const float4 b1v = *(const float4*)&sb1[c4];

            #pragma unroll
            for (int i = 0; i < 6; i++) {
                const int pair = slot * 6 + i;
                const int item = pair / 3, p = pair - item * 3;
                const float* xp = &sx[item * 20 + p * 4];
                float xv[12];
                *(float4*)&xv[0] = *(const float4*)xp;
                *(float4*)&xv[4] = *(const float4*)(xp + 4);
                *(float4*)&xv[8] = *(const float4*)(xp + 8);
                float4 a = b1v;
                #pragma unroll
                for (int rd = 0; rd < 12; rd++) {
                    a.x += xv[rd] * w1r[rd].x;
                    a.y += xv[rd] * w1r[rd].y;
                    a.z += xv[rd] * w1r[rd].z;
                    a.w += xv[rd] * w1r[rd].w;
                }
                a.x = fmaxf(a.x, 0.f); a.y = fmaxf(a.y, 0.f);
                a.z = fmaxf(a.z, 0.f); a.w = fmaxf(a.w, 0.f);
                *(float4*)&sh[item * 96 + p * 32 + c4] = a;
            }
        }
        __syncthreads();

        {
            const int fq = tid & 15, rq = tid >> 4;
            const int f0 = fq * 4;
            const int it0 = rq * 4;

            float2 ac[4][2] = {};
            #pragma unroll 4
            for (int k = 0; k < 96; k++) {
                float4 wv = *(const float4*)&sW2[k * 64 + f0];
                float2 w0 = make_float2(wv.x, wv.y), w1 = make_float2(wv.z, wv.w);
                float h0 = sh[(it0 + 0) * 96 + k];
                float h1 = sh[(it0 + 1) * 96 + k];
                float h2 = sh[(it0 + 2) * 96 + k];
                float h3 = sh[(it0 + 3) * 96 + k];
                float2 d0 = make_float2(h0, h0), d1 = make_float2(h1, h1);
                float2 d2 = make_float2(h2, h2), d3 = make_float2(h3, h3);
                fma2(ac[0][0], d0, w0); fma2(ac[0][1], d0, w1);
                fma2(ac[1][0], d1, w0); fma2(ac[1][1], d1, w1);
                fma2(ac[2][0], d2, w0); fma2(ac[2][1], d2, w1);
                fma2(ac[3][0], d3, w0); fma2(ac[3][1], d3, w1);
            }
            const float bz0 = sb2[f0], bz1 = sb2[f0 + 1];
            const float bz2 = sb2[f0 + 2], bz3 = sb2[f0 + 3];
            #pragma unroll
            for (int i = 0; i < 4; i++) {
                const int item = it0 + i;
                const int b = item >> 4, nloc = item & 15;
                const int n = n0 + nloc;
                float4 cv;
                cv.x = ac[i][0].x + bz0;
                cv.y = ac[i][0].y + bz1;
                cv.z = ac[i][1].x + bz2;
                cv.w = ac[i][1].y + bz3;
                *(float4*)&g_cond[(size_t)n * CF + b * 64 + f0] = cv;
                scT[(b * 64 + f0 + 0) * 16 + nloc] = __float2bfloat16(cv.x);
                scT[(b * 64 + f0 + 1) * 16 + nloc] = __float2bfloat16(cv.y);
                scT[(b * 64 + f0 + 2) * 16 + nloc] = __float2bfloat16(cv.z);
                scT[(b * 64 + f0 + 3) * 16 + nloc] = __float2bfloat16(cv.w);
            }
        }
        __syncthreads();

        for (int i = tid; i < 512; i += 256) {
            const int row = i >> 1, half = i & 1;
            *(int4*)((char*)(g_condT + (size_t)row * NN + n0) + half * 16) =
                *(int4*)((char*)(scT + row * 16) + half * 16);
        }
    }
}

// ---------------------------------------------------------------------------
// Kernel 2: S = A @ cond. grid (32 m-tiles, 4 k-splits) x 256 threads.
// CTA: M=128 x N=256 x K=1024.
// sm_103a pass: tcgen05 SS bf16 with SW128 smem tiles + TMEM accumulator.
// family pass:  HMMA fallback (two 64-row halves, R11 structure).
// ---------------------------------------------------------------------------
__global__ __launch_bounds__(256) void gemm_tc(float* __restrict__ dummy)
{
    extern __shared__ __align__(16) char smem[];
    const int tid  = threadIdx.x;
    const int wid  = tid >> 5;
    const int lane = tid & 31;
    const int z    = blockIdx.y;
    const int ks0  = z * (NN / TC_KSPLIT);

#if defined(__CUDA_ARCH__) && (defined(__CUDA_ARCH_FEAT_SM103_ALL) || defined(__CUDA_ARCH_FEAT_SM100_ALL) || defined(__CUDA_ARCH_FEAT_SM101_ALL))
    // ======================= tcgen05 path =======================
    const int j0 = blockIdx.x * TC_M;
    const uint32_t smem_base = smem_u32(smem);
    const uint32_t mbar0 = smem_base + 16;   // 3 mbarriers at +16,+24,+32

    if (wid == 0) {
        asm volatile(
            "tcgen05.alloc.cta_group::1.sync.aligned.shared::cta.b32 [%0], %1;"
            :: "r"(smem_base), "r"(256u) : "memory");
    }
    if (tid == 0) {
        mbar_init(mbar0, 1);
        mbar_init(mbar0 + 8, 1);
        mbar_init(mbar0 + 16, 1);
    }
    __syncthreads();
    uint32_t tmem;
    asm volatile("ld.shared.b32 %0, [%1];" : "=r"(tmem) : "r"(smem_base));

    // 1024-aligned data region (SW128 tile base must be swizzle-aligned)
    char* const data0 = (char*)(((uintptr_t)smem + 64 + 1023) & ~(uintptr_t)1023);

    auto load_B = [&](int slot, int kt) {
        char* Bb = data0 + slot * TC_BUF + TC_AB;
        const int k = ks0 + kt * TC_KT;
        #pragma unroll
        for (int u = 0; u < 8; u++) {
            const int ch = u * 256 + tid;        // 0..2047
            const int rw = ch >> 3, off = ch & 7;
            cp_async16(Bb + SWZ(rw * 128 + off * 16),
                       g_condT + (size_t)rw * NN + k + off * 8);
        }
        cp_async_commit();
    };
    auto load_A = [&](int slot, int kt) {
        char* Ab = data0 + slot * TC_BUF;
        const int k = ks0 + kt * TC_KT;
        const int wordbase = k >> 5;
        #pragma unroll
        for (int u = 0; u < 4; u++) {
            const int idx = u * 256 + tid;       // 0..1023
            const int rw = idx >> 3, off = idx & 7;
            unsigned word = g_Abits[(size_t)(j0 + rw) * NSEG + wordbase + (off >> 2)];
            unsigned bits = (word >> ((off & 3) * 8)) & 0xFFu;
            uint32_t p0 = ((bits >> 0) & 1u ? 0x3F80u : 0u) | ((bits >> 1) & 1u ? 0x3F800000u : 0u);
            uint32_t p1 = ((bits >> 2) & 1u ? 0x3F80u : 0u) | ((bits >> 3) & 1u ? 0x3F800000u : 0u);
            uint32_t p2 = ((bits >> 4) & 1u ? 0x3F80u : 0u) | ((bits >> 5) & 1u ? 0x3F800000u : 0u);
            uint32_t p3 = ((bits >> 6) & 1u ? 0x3F80u : 0u) | ((bits >> 7) & 1u ? 0x3F800000u : 0u);
            *(uint4*)(Ab + SWZ(rw * 128 + off * 16)) = make_uint4(p0, p1, p2, p3);
        }
    };

    load_B(0, 0);
    load_B(1, 1);
    load_A(0, 0);
    load_A(1, 1);
    fence_proxy_async_cta();
    cp_async_wait<1>();     // buffer 0's B complete
    __syncthreads();

    #pragma unroll 1
    for (int kt = 0; kt < TC_NKT; kt++) {
        const int cur = kt % 3;

        if (wid == 0) {
            if (elect_one()) {
                char* Ab = data0 + cur * TC_BUF;
                char* Bb = Ab + TC_AB;
                uint64_t ad = make_desc_sw128(smem_u32(Ab));
                uint64_t bd = make_desc_sw128(smem_u32(Bb));
                #pragma unroll
                for (int k = 0; k < 4; k++)
                    tc_mma_f16_ss(tmem, ad + k * 2, bd + k * 2, TC_IDESC,
                                  (kt > 0) || (k > 0));
                tc_commit(mbar0 + cur * 8);
            }
        }

        if (kt + 2 < TC_NKT) {
            if (kt >= 1)
                mbar_wait(mbar0 + ((kt - 1) % 3) * 8, ((kt - 1) / 3) & 1);
            load_B((kt + 2) % 3, kt + 2);
            load_A((kt + 2) % 3, kt + 2);
            fence_proxy_async_cta();
        }
        if (kt + 1 < TC_NKT) cp_async_wait<1>(); else cp_async_wait<0>();
        __syncthreads();
    }

    mbar_wait(mbar0 + ((TC_NKT - 1) % 3) * 8, ((TC_NKT - 1) / 3) & 1);
    asm volatile("tcgen05.fence::after_thread_sync;" ::: "memory");

    if (wid < 4) {
        float* Sp = g_Spart[z];
        const int r = j0 + wid * 32 + lane;
        #pragma unroll 1
        for (int c0 = 0; c0 < 8; c0++) {
            uint32_t d[32];
            asm volatile(
                "tcgen05.ld.sync.aligned.32x32b.x32.b32 "
                "{%0,%1,%2,%3,%4,%5,%6,%7,%8,%9,%10,%11,%12,%13,%14,%15,"
                "%16,%17,%18,%19,%20,%21,%22,%23,%24,%25,%26,%27,%28,%29,%30,%31}, [%32];"
                : "=r"(d[0]), "=r"(d[1]), "=r"(d[2]), "=r"(d[3]),
                  "=r"(d[4]), "=r"(d[5]), "=r"(d[6]), "=r"(d[7]),
                  "=r"(d[8]), "=r"(d[9]), "=r"(d[10]), "=r"(d[11]),
                  "=r"(d[12]), "=r"(d[13]), "=r"(d[14]), "=r"(d[15]),
                  "=r"(d[16]), "=r"(d[17]), "=r"(d[18]), "=r"(d[19]),
                  "=r"(d[20]), "=r"(d[21]), "=r"(d[22]), "=r"(d[23]),
                  "=r"(d[24]), "=r"(d[25]), "=r"(d[26]), "=r"(d[27]),
                  "=r"(d[28]), "=r"(d[29]), "=r"(d[30]), "=r"(d[31])
                : "r"(tmem + c0 * 32));
            asm volatile("tcgen05.wait::ld.sync.aligned;" ::: "memory");
            #pragma unroll
            for (int q = 0; q < 8; q++) {
                *(float4*)&Sp[(size_t)r * CF + c0 * 32 + q * 4] =
                    make_float4(__uint_as_float(d[q * 4 + 0]),
                                __uint_as_float(d[q * 4 + 1]),
                                __uint_as_float(d[q * 4 + 2]),
                                __uint_as_float(d[q * 4 + 3]));
            }
        }
    }
    __syncthreads();
    if (wid == 0) {
        asm volatile("tcgen05.relinquish_alloc_permit.cta_group::1.sync.aligned;");
        asm volatile("tcgen05.dealloc.cta_group::1.sync.aligned.b32 %0, %1;"
                     :: "r"(tmem), "r"(256u));
    }
#else
    // ======================= HMMA fallback =======================
    const unsigned smem_u = smem_u32(smem);
    const int g    = lane >> 2;
    const int t    = lane & 3;
    const int mi2  = wid >> 2;
    const int nj   = wid & 3;

    const int aoff = (mi2 * 32 + ((lane >> 3) & 1) * 8 + (lane & 7)) * FB_LDSB
                   + (lane >> 4) * 16;
    const int boff = (nj * 64 + (lane >> 4) * 8 + (lane & 7)) * FB_LDSB
                   + ((lane >> 3) & 1) * 16;
    const int erow = tid >> 2;
    const int etq  = tid & 3;

    #pragma unroll 1
    for (int mh = 0; mh < 2; mh++) {
        const int j0h = blockIdx.x * TC_M + mh * 64;
        const unsigned* ebits = g_Abits + (size_t)(j0h + erow) * NSEG + (ks0 >> 5);
        char* const astore_base = smem + erow * FB_LDSB + etq * 16;

        float acc[2][8][4] = {};

        auto load_Bf = [&](int slot, int kt_abs) {
            char* base = smem + slot * FB_GT + FB_AT;
            const int k = ks0 + kt_abs * FB_KT;
            #pragma unroll
            for (int u = 0; u < 4; u++) {
                const int ch = u * 256 + tid;
                const int rw = ch >> 2, off = ch & 3;
                cp_async16(base + rw * FB_LDSB + off * 16,
                           g_condT + (size_t)rw * NN + k + off * 8);
            }
            cp_async_commit();
        };
        auto expand_Af = [&](int slot, unsigned w) {
            const unsigned bits = (w >> (etq * 8)) & 0xFFu;
            uint32_t p[4];
            #pragma unroll
            for (int i = 0; i < 4; i++)
                p[i] = ((bits >> (2 * i)) & 1u ? 0x3F80u : 0u)
                     | ((bits >> (2 * i + 1)) & 1u ? 0x3F800000u : 0u);
            *(uint4*)(astore_base + slot * FB_GT) = make_uint4(p[0], p[1], p[2], p[3]);
        };

        {
            unsigned w0 = __ldg(ebits + 0);
            unsigned w1 = __ldg(ebits + 1);
            load_Bf(0, 0);
            load_Bf(1, 1);
            expand_Af(0, w0);
            expand_Af(1, w1);
        }
        cp_async_wait<1>();
        __syncthreads();

        #pragma unroll 1
        for (int kt = 0; kt < FB_NKT; kt++) {
            unsigned wnext = 0;
            if (kt + 2 < FB_NKT) {
                wnext = __ldg(ebits + kt + 2);
                load_Bf((kt + 2) % 3, kt + 2);
            }

            const unsigned Au = smem_u + (kt % 3) * FB_GT;
            const unsigned Bu = Au + FB_AT;

            #pragma unroll
            for (int kk = 0; kk < 2; kk++) {
                const int kb = kk * 32;
                uint32_t a0[4], a1[4];
                ldsm_x4(a0[0], a0[1], a0[2], a0[3], Au + aoff + kb);
                ldsm_x4(a1[0], a1[1], a1[2], a1[3], Au + aoff + 16 * FB_LDSB + kb);
                #pragma unroll
                for (int nb = 0; nb < 4; nb++) {
                    uint32_t b[4];
                    ldsm_x4(b[0], b[1], b[2], b[3],
                            Bu + boff + nb * 16 * FB_LDSB + kb);
                    mma_bf16_v(acc[0][nb * 2],     a0[0], a0[1], a0[2], a0[3], b[0], b[1]);
                    mma_bf16_v(acc[0][nb * 2 + 1], a0[0], a0[1], a0[2], a0[3], b[2], b[3]);
                    mma_bf16_v(acc[1][nb * 2],     a1[0], a1[1], a1[2], a1[3], b[0], b[1]);
                    mma_bf16_v(acc[1][nb * 2 + 1], a1[0], a1[1], a1[2], a1[3], b[2], b[3]);
                }
            }

            if (kt + 2 < FB_NKT) {
                expand_Af((kt + 2) % 3, wnext);
                cp_async_wait<1>();
            } else {
                cp_async_wait<0>();
            }
            __syncthreads();
        }

        float* Sp = g_Spart[z];
        #pragma unroll
        for (int h = 0; h < 2; h++) {
            const int r = mi2 * 32 + h * 16 + g;
            #pragma unroll
            for (int ni = 0; ni < 8; ni++) {
                const int col = nj * 64 + ni * 8 + 2 * t;
                *(float2*)&Sp[(size_t)(j0h + r) * CF + col] =
                    make_float2(acc[h][ni][0], acc[h][ni][1]);
                *(float2*)&Sp[(size_t)(j0h + r + 8) * CF + col] =
                    make_float2(acc[h][ni][2], acc[h][ni][3]);
            }
        }
        __syncthreads();
    }
#endif
}

// ---------------------------------------------------------------------------
// Kernel 3: epilogue — combine K-split partials + GEMV chain. (unchanged)
// ---------------------------------------------------------------------------
__global__ __launch_bounds__(256) void epi_kernel(
    const float* __restrict__ ts,
    const float* __restrict__ Wg1, const float* __restrict__ bg,
    const float* __restrict__ Wd,  const float* __restrict__ bd,
    const float* __restrict__ Wo,  const float* __restrict__ bo,
    float* __restrict__ out)
{
    extern __shared__ float sm[];
    float* agg  = sm;
    float* cnd  = sm + 4096;
    float* sW   = sm + 8192;
    float* sWo  = sm + 16384;
    float* sbg  = sm + 16640;
    float* sbd  = sm + 16704;
    float* sbo  = sm + 16768;
    float* sinv = sm + 16832;
    float* sal  = sm + 16896;
    float* sdg  = sm + 16960;

    const int tid = threadIdx.x;
    const int b   = blockIdx.x;
    const int j0  = blockIdx.y * 64;
    const int cb  = b * 64;

    if (tid < 64) {
        const int j = j0 + tid;
        sinv[tid] = g_invdeg[j];
        unsigned dw = g_Abits[(size_t)j * NSEG + (j >> 5)];
        sdg[tid] = ((dw >> (j & 31)) & 1u) ? 1.f : 0.f;
        unsigned aw = g_colOr[j >> 5];
        sal[tid] = ((aw >> (j & 31)) & 1u) ? 1.f : 0.f;
    }
    for (int i = tid; i < 4096; i += 256) sW[i] = Wg1[i];
    if (tid < 256) sWo[tid] = Wo[tid];
    if (tid < 64) { sbg[tid] = bg[tid]; sbd[tid] = bd[tid]; }
    if (tid < 4)  sbo[tid] = bo[tid];
    __syncthreads();

    for (int idx = tid; idx < 4096; idx += 256) {
        const int r = idx >> 6, c = idx & 63;
        const size_t gix = (size_t)(j0 + r) * CF + cb + c;
        const float cv = g_cond[gix];
        const float s  = g_Spart[0][gix] + g_Spart[1][gix]
                       + g_Spart[2][gix] + g_Spart[3][gix];
        cnd[r * 64 + c] = cv;
        agg[r * 64 + c] = (s - sdg[r] * cv) * sinv[r];
    }
    __syncthreads();

    const int fq = tid & 15, rq = tid >> 4;
    const int f0 = fq * 4, r0 = rq * 4;

    float2 ac[4][2] = {};
    #pragma unroll 4
    for (int i = 0; i < 64; i++) {
        float4 wv = *(const float4*)&sW[i * 64 + f0];
        float2 w0 = make_float2(wv.x, wv.y), w1 = make_float2(wv.z, wv.w);
        float a0 = agg[(r0 + 0) * 64 + i];
        float a1 = agg[(r0 + 1) * 64 + i];
        float a2 = agg[(r0 + 2) * 64 + i];
        float a3 = agg[(r0 + 3) * 64 + i];
        float2 d0 = make_float2(a0, a0), d1 = make_float2(a1, a1);
        float2 d2 = make_float2(a2, a2), d3 = make_float2(a3, a3);
        fma2(ac[0][0], d0, w0); fma2(ac[0][1], d0, w1);
        fma2(ac[1][0], d1, w0); fma2(ac[1][1], d1, w1);
        fma2(ac[2][0], d2, w0); fma2(ac[2][1], d2, w1);
        fma2(ac[3][0], d3, w0); fma2(ac[3][1], d3, w1);
    }
    float Gv[4][4];
    #pragma unroll
    for (int ri = 0; ri < 4; ri++) {
        const float al = sal[r0 + ri];
        Gv[ri][0] = tanhf(ac[ri][0].x + sbg[f0 + 0]) * al;
        Gv[ri][1] = tanhf(ac[ri][0].y + sbg[f0 + 1]) * al;
        Gv[ri][2] = tanhf(ac[ri][1].x + sbg[f0 + 2]) * al;
        Gv[ri][3] = tanhf(ac[ri][1].y + sbg[f0 + 3]) * al;
    }
    __syncthreads();
    #pragma unroll
    for (int ri = 0; ri < 4; ri++)
        *(float4*)&agg[(r0 + ri) * 64 + f0] =
            make_float4(Gv[ri][0], Gv[ri][1], Gv[ri][2], Gv[ri][3]);
    for (int i = tid; i < 8192; i += 256) sW[i] = Wd[i];
    __syncthreads();

    float2 hc[4][2] = {};
    #pragma unroll 4
    for (int i = 0; i < 64; i++) {
        float4 wv = *(const float4*)&sW[i * 64 + f0];
        float2 w0 = make_float2(wv.x, wv.y), w1 = make_float2(wv.z, wv.w);
        float c0v = cnd[(r0 + 0) * 64 + i];
        float c1v = cnd[(r0 + 1) * 64 + i];
        float c2v = cnd[(r0 + 2) * 64 + i];
        float c3v = cnd[(r0 + 3) * 64 + i];
        float2 d0 = make_float2(c0v, c0v), d1 = make_float2(c1v, c1v);
        float2 d2 = make_float2(c2v, c2v), d3 = make_float2(c3v, c3v);
        fma2(hc[0][0], d0, w0); fma2(hc[0][1], d0, w1);
        fma2(hc[1][0], d1, w0); fma2(hc[1][1], d1, w1);
        fma2(hc[2][0], d2, w0); fma2(hc[2][1], d2, w1);
        fma2(hc[3][0], d3, w0); fma2(hc[3][1], d3, w1);
    }
    #pragma unroll 4
    for (int i = 0; i < 64; i++) {
        float4 wv = *(const float4*)&sW[(64 + i) * 64 + f0];
        float2 w0 = make_float2(wv.x, wv.y), w1 = make_float2(wv.z, wv.w);
        float g0 = agg[(r0 + 0) * 64 + i];
        float g1 = agg[(r0 + 1) * 64 + i];
        float g2 = agg[(r0 + 2) * 64 + i];
        float g3 = agg[(r0 + 3) * 64 + i];
        float2 d0 = make_float2(g0, g0), d1 = make_float2(g1, g1);
        float2 d2 = make_float2(g2, g2), d3 = make_float2(g3, g3);
        fma2(hc[0][0], d0, w0); fma2(hc[0][1], d0, w1);
        fma2(hc[1][0], d1, w0); fma2(hc[1][1], d1, w1);
        fma2(hc[2][0], d2, w0); fma2(hc[2][1], d2, w1);
        fma2(hc[3][0], d3, w0); fma2(hc[3][1], d3, w1);
    }
    float Hv[4][4];
    #pragma unroll
    for (int ri = 0; ri < 4; ri++) {
        Hv[ri][0] = fmaxf(hc[ri][0].x + sbd[f0 + 0], 0.f);
        Hv[ri][1] = fmaxf(hc[ri][0].y + sbd[f0 + 1], 0.f);
        Hv[ri][2] = fmaxf(hc[ri][1].x + sbd[f0 + 2], 0.f);
        Hv[ri][3] = fmaxf(hc[ri][1].y + sbd[f0 + 3], 0.f);
    }
    __syncthreads();
    #pragma unroll
    for (int ri = 0; ri < 4; ri++)
        *(float4*)&cnd[(r0 + ri) * 64 + f0] =
            make_float4(Hv[ri][0], Hv[ri][1], Hv[ri][2], Hv[ri][3]);
    __syncthreads();

    {
        const int r = tid >> 2, d = tid & 3;
        const int j = j0 + r;
        float o = sbo[d];
        #pragma unroll
        for (int f = 0; f < 64; f++) o += cnd[r * 64 + f] * sWo[f * DD + d];
        const float last = ts[((size_t)(b * TT + 4) * NN + j) * DD + d];
        out[((size_t)b * NN + j) * DD + d] = last + tanhf(o);
    }
}

// ---------------------------------------------------------------------------
// Inputs (metadata order): time_segs, edges, Wc1, bc1, Wc2, bc2,
//                          Wg1, bg, Wd, bd, Wo, bo
// ---------------------------------------------------------------------------
extern "C" void kernel_launch(void* const* d_in, const int* in_sizes, int n_in,
                              void* d_out, int out_size)
{
    const float* ts   = (const float*)d_in[0];
    const int*   edges= (const int*)  d_in[1];
    const float* Wc1  = (const float*)d_in[2];
    const float* bc1  = (const float*)d_in[3];
    const float* Wc2  = (const float*)d_in[4];
    const float* bc2  = (const float*)d_in[5];
    const float* Wg1  = (const float*)d_in[6];
    const float* bg   = (const float*)d_in[7];
    const float* Wd   = (const float*)d_in[8];
    const float* bd   = (const float*)d_in[9];
    const float* Wo   = (const float*)d_in[10];
    const float* bo   = (const float*)d_in[11];
    float* out = (float*)d_out;

    static bool attr_done = false;
    if (!attr_done) {
        cudaFuncSetAttribute(fused_prep_cond,
                             cudaFuncAttributeMaxDynamicSharedMemorySize, PREPCOND_SMEM);
        cudaFuncSetAttribute(gemm_tc,
                             cudaFuncAttributeMaxDynamicSharedMemorySize, TC_SMEM);
        cudaFuncSetAttribute(epi_kernel,
                             cudaFuncAttributeMaxDynamicSharedMemorySize, EPI_SMEM);
        attr_done = true;
    }

    fused_prep_cond<<<768, 256, PREPCOND_SMEM>>>(edges, ts, Wc1, bc1, Wc2, bc2);
    gemm_tc<<<dim3(NN / TC_M, TC_KSPLIT), 256, TC_SMEM>>>(out);
    epi_kernel<<<dim3(BB, NN / 64), 256, EPI_SMEM>>>(ts, Wg1, bg, Wd, bd,
                                                     Wo, bo, out);
}

// round 14
// speedup vs baseline: 1.5324x; 1.0018x over previous
#include <cuda_runtime.h>
#include <cuda_bf16.h>
#include <math.h>
#include <stdint.h>

// Problem constants
#define NN   4096
#define BB   4
#define DD   4
#define TT   5
#define F1C  32
#define F2C  64
#define CF   256            // BB * F2C columns of cond matrix

// tcgen05 GEMM tiling
#define TC_M     128
#define TC_N     256                      // all cond columns
#define TC_KT    64                       // 64 bf16 = 128 B per smem row
#define TC_KSPLIT 4
#define TC_NKT   (NN / TC_KSPLIT / TC_KT) // 16 k-tiles per CTA
#define TC_AB    (TC_M * 128)             // 16384
#define TC_BB    (TC_N * 128)             // 32768
#define TC_BUF   (TC_AB + TC_BB)          // 49152
#define TC_SMEM  (2048 + 3 * TC_BUF)      // 149504

#define EPI_SMEM  (17024 * 4)             // 68096
#define COND_SMEM 64512

// idesc: dtype F32, atype/btype BF16, N=256, M=128 (kind::f16)
#define TC_IDESC ((1u<<4) | (1u<<7) | (1u<<10) | ((TC_N/8)<<17) | ((TC_M>>4)<<24))

#define SWZ(x) ((x) ^ (((x) >> 3) & 0x70))

// Scratch (device globals — no allocation allowed)
__device__ float          g_cond[NN * CF];        // cond fp32 [n][b*64+f]
__device__ __nv_bfloat16  g_condT[CF * NN];       // cond bf16 transposed [c][n]
__device__ int            g_deg[NN];              // row degree (atomicAdd)
__device__ unsigned       g_colOr[NN / 32];       // column-nonzero bitmask
__device__ float          g_Spart[TC_KSPLIT][NN * CF]; // K-split partials

// ---------------------------------------------------------------------------
// helpers
// ---------------------------------------------------------------------------
__device__ __forceinline__ void cp_async16(void* smem_dst, const void* gmem_src) {
    unsigned saddr = (unsigned)__cvta_generic_to_shared(smem_dst);
    asm volatile("cp.async.cg.shared.global [%0], [%1], 16;\n"
                 :: "r"(saddr), "l"(gmem_src) : "memory");
}
__device__ __forceinline__ void cp_async_commit() {
    asm volatile("cp.async.commit_group;\n" ::: "memory");
}
template <int N>
__device__ __forceinline__ void cp_async_wait() {
    asm volatile("cp.async.wait_group %0;\n" :: "n"(N) : "memory");
}
__device__ __forceinline__ void fma2(float2 &a, const float2 &x, const float2 &y) {
    unsigned long long &ar = reinterpret_cast<unsigned long long &>(a);
    const unsigned long long &xr = reinterpret_cast<const unsigned long long &>(x);
    const unsigned long long &yr = reinterpret_cast<const unsigned long long &>(y);
    asm("fma.rn.f32x2 %0, %1, %2, %0;" : "+l"(ar) : "l"(xr), "l"(yr));
}
__device__ __forceinline__ uint32_t smem_u32(const void* p) {
    return (uint32_t)__cvta_generic_to_shared(p);
}
__device__ __forceinline__ uint32_t elect_one() {
    uint32_t pred;
    asm volatile("{\n\t.reg .pred p;\n\telect.sync _|p, 0xFFFFFFFF;\n\t"
                 "selp.b32 %0, 1, 0, p;\n\t}" : "=r"(pred));
    return pred;
}
__device__ __forceinline__ uint64_t make_desc_sw128(uint32_t addr) {
    const uint64_t base = (uint64_t(2) << 61) | (uint64_t(1) << 46)
                        | (uint64_t(64) << 32) | (uint64_t(1) << 16);
    return base | ((uint64_t)(addr >> 4) & 0x3FFF);
}
__device__ __forceinline__ void tc_mma_f16_ss(uint32_t d, uint64_t ad,
                                              uint64_t bd, uint32_t idesc,
                                              bool en) {
    uint32_t e = en ? 1u : 0u;
    asm volatile(
        "{\n\t.reg .pred p;\n\tsetp.ne.u32 p, %5, 0;\n\t"
        "tcgen05.mma.cta_group::1.kind::f16 [%0], %1, %2, %3, {%4, %4, %4, %4}, p;\n\t}"
        :: "r"(d), "l"(ad), "l"(bd), "r"(idesc), "r"(0u), "r"(e) : "memory");
}
__device__ __forceinline__ void mbar_init(uint32_t a, uint32_t cnt) {
    asm volatile("mbarrier.init.shared.b64 [%0], %1;" :: "r"(a), "r"(cnt) : "memory");
}
__device__ __forceinline__ void tc_commit(uint32_t mbar) {
    asm volatile(
        "tcgen05.commit.cta_group::1.mbarrier::arrive::one.shared::cluster.b64 [%0];"
        :: "r"(mbar) : "memory");
}
__device__ __forceinline__ void mbar_wait(uint32_t mbar, uint32_t parity) {
    uint32_t done;
    asm volatile(
        "{\n\t.reg .pred p;\n\t"
        "mbarrier.try_wait.parity.acquire.cta.shared::cta.b64 p, [%1], %2;\n\t"
        "selp.b32 %0, 1, 0, p;\n\t}"
        : "=r"(done) : "r"(mbar), "r"(parity) : "memory");
    if (!done) {
        asm volatile(
            "{\n\t.reg .pred P1;\n\t"
            "WL_%=:\n\t"
            "mbarrier.try_wait.parity.acquire.cta.shared::cta.b64 P1, [%0], %1, 0x989680;\n\t"
            "@P1 bra.uni WD_%=;\n\t"
            "bra.uni WL_%=;\n\t"
            "WD_%=:\n\t}"
            :: "r"(mbar), "r"(parity) : "memory");
    }
}
__device__ __forceinline__ void fence_proxy_async_cta() {
    asm volatile("fence.proxy.async.shared::cta;" ::: "memory");
}

// ---------------------------------------------------------------------------
// Kernel 1: cond (standalone) + zeroing of g_deg / g_colOr.
// grid 256 x 256; CTA = 16 n x 4 b = 64 items.
// ---------------------------------------------------------------------------
__global__ __launch_bounds__(256) void cond_kernel(
    const float* __restrict__ ts,
    const float* __restrict__ Wc1, const float* __restrict__ bc1,
    const float* __restrict__ Wc2, const float* __restrict__ bc2)
{
    extern __shared__ __align__(16) float pool[];
    const int tid  = threadIdx.x;

    // zero accumulators for this launch (stream-ordered before gemm)
    if (tid < 16) g_deg[blockIdx.x * 16 + tid] = 0;
    if (blockIdx.x == 0 && tid < NN / 32) g_colOr[tid] = 0u;

    float* sW1 = pool;                 // 384
    float* sW2 = pool + 384;           // 6144
    float* sb1 = pool + 6528;          // 32
    float* sb2 = pool + 6560;          // 64
    float* sx  = pool + 6624;          // 64 x 20 = 1280
    float* sh  = pool + 7904;          // 64 x 96 = 6144
    __nv_bfloat16* scT = (__nv_bfloat16*)(pool + 14048); // 256 x 16 bf16

    const int n0 = blockIdx.x * 16;

    for (int i = tid; i < 3 * DD * F1C; i += 256) sW1[i] = Wc1[i];
    for (int i = tid; i < 3 * F1C * F2C; i += 256) sW2[i] = Wc2[i];
    if (tid < F1C) sb1[tid] = bc1[tid];
    else if (tid < F1C + F2C) sb2[tid - F1C] = bc2[tid - F1C];

    for (int i = tid; i < 1280; i += 256) {
        const int bt  = i >> 6;
        const int rem = i & 63;
        const int b = bt / 5, t = bt - b * 5;
        const int nloc = rem >> 2, d = rem & 3;
        sx[(b * 16 + nloc) * 20 + t * 4 + d] =
            ts[(size_t)bt * (NN * 4) + n0 * 4 + rem];
    }
    __syncthreads();

    {
        const int c4   = (tid & 7) * 4;
        const int slot = tid >> 3;
        float4 w1r[12];
        #pragma unroll
        for (int rd = 0; rd < 12; rd++)
            w1r[rd] = *(const float4*)&sW1[rd * F1C + c4];
        const float4 b1v = *(const float4*)&sb1[c4];

        #pragma unroll
        for (int i = 0; i < 6; i++) {
            const int pair = slot * 6 + i;
            const int item = pair / 3, p = pair - item * 3;
            const float* xp = &sx[item * 20 + p * 4];
            float xv[12];
            *(float4*)&xv[0] = *(const float4*)xp;
            *(float4*)&xv[4] = *(const float4*)(xp + 4);
            *(float4*)&xv[8] = *(const float4*)(xp + 8);
            float4 a = b1v;
            #pragma unroll
            for (int rd = 0; rd < 12; rd++) {
                a.x += xv[rd] * w1r[rd].x;
                a.y += xv[rd] * w1r[rd].y;
                a.z += xv[rd] * w1r[rd].z;
                a.w += xv[rd] * w1r[rd].w;
            }
            a.x = fmaxf(a.x, 0.f); a.y = fmaxf(a.y, 0.f);
            a.z = fmaxf(a.z, 0.f); a.w = fmaxf(a.w, 0.f);
            *(float4*)&sh[item * 96 + p * 32 + c4] = a;
        }
    }
    __syncthreads();

    {
        const int fq = tid & 15, rq = tid >> 4;
        const int f0 = fq * 4;
        const int it0 = rq * 4;

        float2 ac[4][2] = {};
        #pragma unroll 4
        for (int k = 0; k < 96; k++) {
            float4 wv = *(const float4*)&sW2[k * 64 + f0];
            float2 w0 = make_float2(wv.x, wv.y), w1 = make_float2(wv.z, wv.w);
            float h0 = sh[(it0 + 0) * 96 + k];
            float h1 = sh[(it0 + 1) * 96 + k];
            float h2 = sh[(it0 + 2) * 96 + k];
            float h3 = sh[(it0 + 3) * 96 + k];
            float2 d0 = make_float2(h0, h0), d1 = make_float2(h1, h1);
            float2 d2 = make_float2(h2, h2), d3 = make_float2(h3, h3);
            fma2(ac[0][0], d0, w0); fma2(ac[0][1], d0, w1);
            fma2(ac[1][0], d1, w0); fma2(ac[1][1], d1, w1);
            fma2(ac[2][0], d2, w0); fma2(ac[2][1], d2, w1);
            fma2(ac[3][0], d3, w0); fma2(ac[3][1], d3, w1);
        }
        const float bz0 = sb2[f0], bz1 = sb2[f0 + 1];
        const float bz2 = sb2[f0 + 2], bz3 = sb2[f0 + 3];
        #pragma unroll
        for (int i = 0; i < 4; i++) {
            const int item = it0 + i;
            const int b = item >> 4, nloc = item & 15;
            const int n = n0 + nloc;
            float4 cv;
            cv.x = ac[i][0].x + bz0;
            cv.y = ac[i][0].y + bz1;
            cv.z = ac[i][1].x + bz2;
            cv.w = ac[i][1].y + bz3;
            *(float4*)&g_cond[(size_t)n * CF + b * 64 + f0] = cv;
            scT[(b * 64 + f0 + 0) * 16 + nloc] = __float2bfloat16(cv.x);
            scT[(b * 64 + f0 + 1) * 16 + nloc] = __float2bfloat16(cv.y);
            scT[(b * 64 + f0 + 2) * 16 + nloc] = __float2bfloat16(cv.z);
            scT[(b * 64 + f0 + 3) * 16 + nloc] = __float2bfloat16(cv.w);
        }
    }
    __syncthreads();

    for (int i = tid; i < 512; i += 256) {
        const int row = i >> 1, half = i & 1;
        *(int4*)((char*)(g_condT + (size_t)row * NN + n0) + half * 16) =
            *(int4*)((char*)(scT + row * 16) + half * 16);
    }
}

// ---------------------------------------------------------------------------
// Kernel 2: tcgen05 GEMM  S = A @ cond reading edges DIRECTLY, with fused
// row-degree (atomicAdd) and column-alive (atomicOr) side computation.
// grid (32 m-tiles, 4 k-splits) x 256 threads. CTA: M=128 x N=256 x K=1024.
// ---------------------------------------------------------------------------
__global__ __launch_bounds__(256) void gemm_tc(const int* __restrict__ edges)
{
    extern __shared__ __align__(16) char smem[];
    const int tid  = threadIdx.x;
    const int wid  = tid >> 5;
    const int lane = tid & 31;
    const int z    = blockIdx.y;
    const int ks0  = z * (NN / TC_KSPLIT);
    const int j0   = blockIdx.x * TC_M;

#if defined(__CUDA_ARCH__) && (defined(__CUDA_ARCH_FEAT_SM103_ALL) || defined(__CUDA_ARCH_FEAT_SM100_ALL) || defined(__CUDA_ARCH_FEAT_SM101_ALL))
    // ======================= tcgen05 path =======================
    const uint32_t smem_base = smem_u32(smem);
    const uint32_t mbar0 = smem_base + 16;           // 3 mbarriers
    unsigned* sOr = (unsigned*)(smem + 64);          // 32 words

    if (wid == 0) {
        asm volatile(
            "tcgen05.alloc.cta_group::1.sync.aligned.shared::cta.b32 [%0], %1;"
            :: "r"(smem_base), "r"(256u) : "memory");
    }
    if (tid == 0) {
        mbar_init(mbar0, 1);
        mbar_init(mbar0 + 8, 1);
        mbar_init(mbar0 + 16, 1);
    }
    if (tid < 32) sOr[tid] = 0u;
    __syncthreads();
    uint32_t tmem;
    asm volatile("ld.shared.b32 %0, [%1];" : "=r"(tmem) : "r"(smem_base));

    char* const data0 = (char*)(((uintptr_t)smem + 256 + 1023) & ~(uintptr_t)1023);

    const int cl = lane & 15;         // int4 (4 k) index within 64-k stage
    const int rh = lane >> 4;         // row parity within pair
    int cnt[8] = {};

    auto load_B = [&](int slot, int kt) {
        char* Bb = data0 + slot * TC_BUF + TC_AB;
        const int k = ks0 + kt * TC_KT;
        #pragma unroll
        for (int u = 0; u < 8; u++) {
            const int ch = u * 256 + tid;
            const int rw = ch >> 3, off = ch & 7;
            cp_async16(Bb + SWZ(rw * 128 + off * 16),
                       g_condT + (size_t)rw * NN + k + off * 8);
        }
        cp_async_commit();
    };
    auto load_E = [&](int4* ev, int kt) {
        const int k = ks0 + kt * TC_KT + cl * 4;
        #pragma unroll
        for (int it = 0; it < 8; it++) {
            const int rloc = wid * 16 + it * 2 + rh;
            ev[it] = *(const int4*)(edges + (size_t)(j0 + rloc) * NN + k);
        }
    };
    auto conv_store = [&](int slot, const int4* ev, int kt) {
        char* Ab = data0 + slot * TC_BUF;
        unsigned nib_or = 0;
        #pragma unroll
        for (int it = 0; it < 8; it++) {
            const int4 v = ev[it];
            const unsigned n0 = v.x != 0, n1 = v.y != 0;
            const unsigned n2 = v.z != 0, n3 = v.w != 0;
            cnt[it] += (int)(n0 + n1 + n2 + n3);
            nib_or |= n0 | (n1 << 1) | (n2 << 2) | (n3 << 3);
            const uint32_t p0 = (n0 ? 0x3F80u : 0u) | (n1 ? 0x3F800000u : 0u);
            const uint32_t p1 = (n2 ? 0x3F80u : 0u) | (n3 ? 0x3F800000u : 0u);
            const int rloc = wid * 16 + it * 2 + rh;
            *(uint2*)(Ab + SWZ(rloc * 128 + cl * 8)) = make_uint2(p0, p1);
        }
        if (nib_or)
            atomicOr(&sOr[kt * 2 + (cl >> 3)], nib_or << ((cl & 7) * 4));
    };

    // --- prologue: stages 0 and 1 ---
    {
        int4 ev0[8], ev1[8];
        load_E(ev0, 0);
        load_E(ev1, 1);
        load_B(0, 0);
        load_B(1, 1);
        conv_store(0, ev0, 0);
        conv_store(1, ev1, 1);
    }
    fence_proxy_async_cta();
    cp_async_wait<1>();
    __syncthreads();

    // --- mainloop ---
    #pragma unroll 1
    for (int kt = 0; kt < TC_NKT; kt++) {
        const int cur = kt % 3;

        int4 evn[8];
        if (kt + 2 < TC_NKT) load_E(evn, kt + 2);   // prefetch (latency hidden)

        if (wid == 0) {
            if (elect_one()) {
                char* Ab = data0 + cur * TC_BUF;
                char* Bb = Ab + TC_AB;
                uint64_t ad = make_desc_sw128(smem_u32(Ab));
                uint64_t bd = make_desc_sw128(smem_u32(Bb));
                #pragma unroll
                for (int k = 0; k < 4; k++)
                    tc_mma_f16_ss(tmem, ad + k * 2, bd + k * 2, TC_IDESC,
                                  (kt > 0) || (k > 0));
                tc_commit(mbar0 + cur * 8);
            }
        }

        if (kt + 2 < TC_NKT) {
            if (kt >= 1)
                mbar_wait(mbar0 + ((kt - 1) % 3) * 8, ((kt - 1) / 3) & 1);
            load_B((kt + 2) % 3, kt + 2);
            conv_store((kt + 2) % 3, evn, kt + 2);
            fence_proxy_async_cta();
        }
        if (kt + 1 < TC_NKT) cp_async_wait<1>(); else cp_async_wait<0>();
        __syncthreads();
    }

    mbar_wait(mbar0 + ((TC_NKT - 1) % 3) * 8, ((TC_NKT - 1) / 3) & 1);
    asm volatile("tcgen05.fence::after_thread_sync;" ::: "memory");

    // --- side outputs: row degree + column alive ---
    #pragma unroll
    for (int it = 0; it < 8; it++) {
        int s = cnt[it];
        s += __shfl_down_sync(0xffffffffu, s, 8, 16);
        s += __shfl_down_sync(0xffffffffu, s, 4, 16);
        s += __shfl_down_sync(0xffffffffu, s, 2, 16);
        s += __shfl_down_sync(0xffffffffu, s, 1, 16);
        if (cl == 0)
            atomicAdd(&g_deg[j0 + wid * 16 + it * 2 + rh], s);
    }
    if (tid < 32 && sOr[tid])
        atomicOr(&g_colOr[(ks0 >> 5) + tid], sOr[tid]);

    // --- TMEM readout to Spart ---
    if (wid < 4) {
        float* Sp = g_Spart[z];
        const int r = j0 + wid * 32 + lane;
        #pragma unroll 1
        for (int c0 = 0; c0 < 8; c0++) {
            uint32_t d[32];
            asm volatile(
                "tcgen05.ld.sync.aligned.32x32b.x32.b32 "
                "{%0,%1,%2,%3,%4,%5,%6,%7,%8,%9,%10,%11,%12,%13,%14,%15,"
                "%16,%17,%18,%19,%20,%21,%22,%23,%24,%25,%26,%27,%28,%29,%30,%31}, [%32];"
                : "=r"(d[0]), "=r"(d[1]), "=r"(d[2]), "=r"(d[3]),
                  "=r"(d[4]), "=r"(d[5]), "=r"(d[6]), "=r"(d[7]),
                  "=r"(d[8]), "=r"(d[9]), "=r"(d[10]), "=r"(d[11]),
                  "=r"(d[12]), "=r"(d[13]), "=r"(d[14]), "=r"(d[15]),
                  "=r"(d[16]), "=r"(d[17]), "=r"(d[18]), "=r"(d[19]),
                  "=r"(d[20]), "=r"(d[21]), "=r"(d[22]), "=r"(d[23]),
                  "=r"(d[24]), "=r"(d[25]), "=r"(d[26]), "=r"(d[27]),
                  "=r"(d[28]), "=r"(d[29]), "=r"(d[30]), "=r"(d[31])
                : "r"(tmem + c0 * 32));
            asm volatile("tcgen05.wait::ld.sync.aligned;" ::: "memory");
            #pragma unroll
            for (int q = 0; q < 8; q++) {
                *(float4*)&Sp[(size_t)r * CF + c0 * 32 + q * 4] =
                    make_float4(__uint_as_float(d[q * 4 + 0]),
                                __uint_as_float(d[q * 4 + 1]),
                                __uint_as_float(d[q * 4 + 2]),
                                __uint_as_float(d[q * 4 + 3]));
            }
        }
    }
    __syncthreads();
    if (wid == 0) {
        asm volatile("tcgen05.relinquish_alloc_permit.cta_group::1.sync.aligned;");
        asm volatile("tcgen05.dealloc.cta_group::1.sync.aligned.b32 %0, %1;"
                     :: "r"(tmem), "r"(256u));
    }
#else
    // ===== dead-code fallback (correct, unoptimized; never runs on 103a) =====
    for (int k = tid; k < NN / TC_KSPLIT; k += 256) {
        unsigned any = 0;
        for (int r = 0; r < TC_M; r++)
            if (edges[(size_t)(j0 + r) * NN + ks0 + k] != 0) { any = 1; break; }
        if (any) atomicOr(&g_colOr[(ks0 + k) >> 5], 1u << ((ks0 + k) & 31));
    }
    for (int r = tid; r < TC_M; r += 256) {
        int s = 0;
        for (int k = 0; k < NN / TC_KSPLIT; k++)
            s += (edges[(size_t)(j0 + r) * NN + ks0 + k] != 0);
        atomicAdd(&g_deg[j0 + r], s);
    }
    for (int t = 0; t < 4; t++) {
        const int task = tid + t * 256;
        const int r = task >> 3, cb = (task & 7) * 32;
        float acc[32];
        #pragma unroll
        for (int c = 0; c < 32; c++) acc[c] = 0.f;
        const int* erow = edges + (size_t)(j0 + r) * NN + ks0;
        for (int k = 0; k < NN / TC_KSPLIT; k++) {
            if (erow[k]) {
                for (int c = 0; c < 32; c++)
                    acc[c] += __bfloat162float(
                        g_condT[(size_t)(cb + c) * NN + ks0 + k]);
            }
        }
        for (int c = 0; c < 32; c++)
            g_Spart[z][(size_t)(j0 + r) * CF + cb + c] = acc[c];
    }
#endif
}

// ---------------------------------------------------------------------------
// Kernel 3: epilogue — combine K-split partials + GEMV chain.
// ---------------------------------------------------------------------------
__global__ __launch_bounds__(256) void epi_kernel(
    const int*   __restrict__ edges,
    const float* __restrict__ ts,
    const float* __restrict__ Wg1, const float* __restrict__ bg,
    const float* __restrict__ Wd,  const float* __restrict__ bd,
    const float* __restrict__ Wo,  const float* __restrict__ bo,
    float* __restrict__ out)
{
    extern __shared__ float sm[];
    float* agg  = sm;
    float* cnd  = sm + 4096;
    float* sW   = sm + 8192;
    float* sWo  = sm + 16384;
    float* sbg  = sm + 16640;
    float* sbd  = sm + 16704;
    float* sbo  = sm + 16768;
    float* sinv = sm + 16832;
    float* sal  = sm + 16896;
    float* sdg  = sm + 16960;

    const int tid = threadIdx.x;
    const int b   = blockIdx.x;
    const int j0  = blockIdx.y * 64;
    const int cb  = b * 64;

    if (tid < 64) {
        const int j = j0 + tid;
        sinv[tid] = 1.0f / fmaxf((float)g_deg[j], 1.0f);
        sdg[tid]  = (edges[(size_t)j * NN + j] != 0) ? 1.f : 0.f;
        unsigned aw = g_colOr[j >> 5];
        sal[tid]  = ((aw >> (j & 31)) & 1u) ? 1.f : 0.f;
    }
    for (int i = tid; i < 4096; i += 256) sW[i] = Wg1[i];
    if (tid < 256) sWo[tid] = Wo[tid];
    if (tid < 64) { sbg[tid] = bg[tid]; sbd[tid] = bd[tid]; }
    if (tid < 4)  sbo[tid] = bo[tid];
    __syncthreads();

    for (int idx = tid; idx < 4096; idx += 256) {
        const int r = idx >> 6, c = idx & 63;
        const size_t gix = (size_t)(j0 + r) * CF + cb + c;
        const float cv = g_cond[gix];
        const float s  = g_Spart[0][gix] + g_Spart[1][gix]
                       + g_Spart[2][gix] + g_Spart[3][gix];
        cnd[r * 64 + c] = cv;
        agg[r * 64 + c] = (s - sdg[r] * cv) * sinv[r];
    }
    __syncthreads();

    const int fq = tid & 15, rq = tid >> 4;
    const int f0 = fq * 4, r0 = rq * 4;

    float2 ac[4][2] = {};
    #pragma unroll 4
    for (int i = 0; i < 64; i++) {
        float4 wv = *(const float4*)&sW[i * 64 + f0];
        float2 w0 = make_float2(wv.x, wv.y), w1 = make_float2(wv.z, wv.w);
        float a0 = agg[(r0 + 0) * 64 + i];
        float a1 = agg[(r0 + 1) * 64 + i];
        float a2 = agg[(r0 + 2) * 64 + i];
        float a3 = agg[(r0 + 3) * 64 + i];
        float2 d0 = make_float2(a0, a0), d1 = make_float2(a1, a1);
        float2 d2 = make_float2(a2, a2), d3 = make_float2(a3, a3);
        fma2(ac[0][0], d0, w0); fma2(ac[0][1], d0, w1);
        fma2(ac[1][0], d1, w0); fma2(ac[1][1], d1, w1);
        fma2(ac[2][0], d2, w0); fma2(ac[2][1], d2, w1);
        fma2(ac[3][0], d3, w0); fma2(ac[3][1], d3, w1);
    }
    float Gv[4][4];
    #pragma unroll
    for (int ri = 0; ri < 4; ri++) {
        const float al = sal[r0 + ri];
        Gv[ri][0] = tanhf(ac[ri][0].x + sbg[f0 + 0]) * al;
        Gv[ri][1] = tanhf(ac[ri][0].y + sbg[f0 + 1]) * al;
        Gv[ri][2] = tanhf(ac[ri][1].x + sbg[f0 + 2]) * al;
        Gv[ri][3] = tanhf(ac[ri][1].y + sbg[f0 + 3]) * al;
    }
    __syncthreads();
    #pragma unroll
    for (int ri = 0; ri < 4; ri++)
        *(float4*)&agg[(r0 + ri) * 64 + f0] =
            make_float4(Gv[ri][0], Gv[ri][1], Gv[ri][2], Gv[ri][3]);
    for (int i = tid; i < 8192; i += 256) sW[i] = Wd[i];
    __syncthreads();

    float2 hc[4][2] = {};
    #pragma unroll 4
    for (int i = 0; i < 64; i++) {
        float4 wv = *(const float4*)&sW[i * 64 + f0];
        float2 w0 = make_float2(wv.x, wv.y), w1 = make_float2(wv.z, wv.w);
        float c0v = cnd[(r0 + 0) * 64 + i];
        float c1v = cnd[(r0 + 1) * 64 + i];
        float c2v = cnd[(r0 + 2) * 64 + i];
        float c3v = cnd[(r0 + 3) * 64 + i];
        float2 d0 = make_float2(c0v, c0v), d1 = make_float2(c1v, c1v);
        float2 d2 = make_float2(c2v, c2v), d3 = make_float2(c3v, c3v);
        fma2(hc[0][0], d0, w0); fma2(hc[0][1], d0, w1);
        fma2(hc[1][0], d1, w0); fma2(hc[1][1], d1, w1);
        fma2(hc[2][0], d2, w0); fma2(hc[2][1], d2, w1);
        fma2(hc[3][0], d3, w0); fma2(hc[3][1], d3, w1);
    }
    #pragma unroll 4
    for (int i = 0; i < 64; i++) {
        float4 wv = *(const float4*)&sW[(64 + i) * 64 + f0];
        float2 w0 = make_float2(wv.x, wv.y), w1 = make_float2(wv.z, wv.w);
        float g0 = agg[(r0 + 0) * 64 + i];
        float g1 = agg[(r0 + 1) * 64 + i];
        float g2 = agg[(r0 + 2) * 64 + i];
        float g3 = agg[(r0 + 3) * 64 + i];
        float2 d0 = make_float2(g0, g0), d1 = make_float2(g1, g1);
        float2 d2 = make_float2(g2, g2), d3 = make_float2(g3, g3);
        fma2(hc[0][0], d0, w0); fma2(hc[0][1], d0, w1);
        fma2(hc[1][0], d1, w0); fma2(hc[1][1], d1, w1);
        fma2(hc[2][0], d2, w0); fma2(hc[2][1], d2, w1);
        fma2(hc[3][0], d3, w0); fma2(hc[3][1], d3, w1);
    }
    float Hv[4][4];
    #pragma unroll
    for (int ri = 0; ri < 4; ri++) {
        Hv[ri][0] = fmaxf(hc[ri][0].x + sbd[f0 + 0], 0.f);
        Hv[ri][1] = fmaxf(hc[ri][0].y + sbd[f0 + 1], 0.f);
        Hv[ri][2] = fmaxf(hc[ri][1].x + sbd[f0 + 2], 0.f);
        Hv[ri][3] = fmaxf(hc[ri][1].y + sbd[f0 + 3], 0.f);
    }
    __syncthreads();
    #pragma unroll
    for (int ri = 0; ri < 4; ri++)
        *(float4*)&cnd[(r0 + ri) * 64 + f0] =
            make_float4(Hv[ri][0], Hv[ri][1], Hv[ri][2], Hv[ri][3]);
    __syncthreads();

    {
        const int r = tid >> 2, d = tid & 3;
        const int j = j0 + r;
        float o = sbo[d];
        #pragma unroll
        for (int f = 0; f < 64; f++) o += cnd[r * 64 + f] * sWo[f * DD + d];
        const float last = ts[((size_t)(b * TT + 4) * NN + j) * DD + d];
        out[((size_t)b * NN + j) * DD + d] = last + tanhf(o);
    }
}

// ---------------------------------------------------------------------------
// Inputs (metadata order): time_segs, edges, Wc1, bc1, Wc2, bc2,
//                          Wg1, bg, Wd, bd, Wo, bo
// ---------------------------------------------------------------------------
extern "C" void kernel_launch(void* const* d_in, const int* in_sizes, int n_in,
                              void* d_out, int out_size)
{
    const float* ts   = (const float*)d_in[0];
    const int*   edges= (const int*)  d_in[1];
    const float* Wc1  = (const float*)d_in[2];
    const float* bc1  = (const float*)d_in[3];
    const float* Wc2  = (const float*)d_in[4];
    const float* bc2  = (const float*)d_in[5];
    const float* Wg1  = (const float*)d_in[6];
    const float* bg   = (const float*)d_in[7];
    const float* Wd   = (const float*)d_in[8];
    const float* bd   = (const float*)d_in[9];
    const float* Wo   = (const float*)d_in[10];
    const float* bo   = (const float*)d_in[11];
    float* out = (float*)d_out;

    static bool attr_done = false;
    if (!attr_done) {
        cudaFuncSetAttribute(cond_kernel,
                             cudaFuncAttributeMaxDynamicSharedMemorySize, COND_SMEM);
        cudaFuncSetAttribute(gemm_tc,
                             cudaFuncAttributeMaxDynamicSharedMemorySize, TC_SMEM);
        cudaFuncSetAttribute(epi_kernel,
                             cudaFuncAttributeMaxDynamicSharedMemorySize, EPI_SMEM);
        attr_done = true;
    }

    cond_kernel<<<NN / 16, 256, COND_SMEM>>>(ts, Wc1, bc1, Wc2, bc2);
    gemm_tc<<<dim3(NN / TC_M, TC_KSPLIT), 256, TC_SMEM>>>(edges);
    epi_kernel<<<dim3(BB, NN / 64), 256, EPI_SMEM>>>(edges, ts, Wg1, bg,
                                                     Wd, bd, Wo, bo, out);
}